// round 5
// baseline (speedup 1.0000x reference)
#include <cuda_runtime.h>
#include <cstdint>
#include <cstddef>

#define BB 16
#define AA 65536
#define TT 32
#define CC 21
#define NB1 2048
#define NB2 4096
#define CAP 262144
#define THR 256

struct State {
    unsigned long long packed[BB][TT];   // force-match argmax keys
    unsigned int forced[BB][AA / 32];    // forced-positive bitmask
    int numpos[BB], nneg[BB], kval[BB], blo[BB], redo[BB], cnt[BB];
    float possum[BB], bboxsum[BB], confl[BB], bboxl[BB];
    float plo[BB];                       // probability threshold (inverse focal)
    unsigned int h0[BB][NB1];            // sampled coarse histogram
    unsigned int fcnt[BB][NB1];          // fallback histogram
    float fsum[BB][NB1];
};
__device__ State g;
__device__ float g_buf[BB][CAP];         // compacted candidate focal values
__device__ float g_maxiou[BB * AA];
__device__ unsigned char g_bestt[BB * AA];

// ---------------------------------------------------------------- helpers
__device__ __forceinline__ void softmax21(float* x) {
    float m = x[0];
#pragma unroll
    for (int c = 1; c < CC; c++) m = fmaxf(m, x[c]);
    float s = 0.f;
#pragma unroll
    for (int c = 0; c < CC; c++) { x[c] = __expf(x[c] - m); s += x[c]; }
    float inv = 1.0f / s;
#pragma unroll
    for (int c = 0; c < CC; c++) x[c] *= inv;
}

__device__ __forceinline__ float focal_fn(float p, bool ispos) {
    float pt = ispos ? p : 1.0f - p;
    float af = ispos ? 0.25f : 0.75f;
    float om = 1.0f - pt;
    return -af * om * om * __logf(fmaxf(pt, 1e-6f));
}

// bin index of a focal value; sign bit masked so -0.0 -> bin 0 (never OOB)
__device__ __forceinline__ int focal_bin(float f) {
    return (int)((__float_as_uint(f) & 0x7FFFFFFFu) >> 20);
}

// Block-wide (exactly 256 threads) descending bin selection over NB bins.
template <int NB, bool WS>
__device__ __forceinline__ void suffix_select(
    const unsigned* hc, const float* hs, long long k,
    unsigned* s_scnt, float* s_ssum,
    int* o_found, int* o_bin, long long* o_cum, float* o_sum)
{
    const int tid = threadIdx.x;          // requires blockDim.x == 256
    const int CH = NB / 256;
    unsigned myc = 0; float myf = 0.f;
#pragma unroll
    for (int j = 0; j < CH; j++) {
        myc += hc[tid * CH + j];
        if (WS) myf += hs[tid * CH + j];
    }
    s_scnt[tid] = myc;
    if (WS) s_ssum[tid] = myf;
    __syncthreads();
    for (int off = 1; off < 256; off <<= 1) {   // inclusive suffix scan
        unsigned vc = (tid + off < 256) ? s_scnt[tid + off] : 0u;
        float vf = 0.f;
        if (WS) vf = (tid + off < 256) ? s_ssum[tid + off] : 0.f;
        __syncthreads();
        s_scnt[tid] += vc;
        if (WS) s_ssum[tid] += vf;
        __syncthreads();
    }
    if (tid == 0) {
        *o_found = ((long long)s_scnt[0] >= k) ? 1 : 0;
        *o_bin = 0; *o_cum = 0; *o_sum = 0.f;
    }
    __syncthreads();
    if (*o_found) {
        long long S = (long long)s_scnt[tid];
        long long A = S - (long long)myc;
        if (A < k && S >= k) {                    // unique crossing chunk
            long long cum = A;
            float ab = WS ? (s_ssum[tid] - myf) : 0.f;
            int bin = tid * CH;
            for (int j = CH - 1; j >= 0; j--) {
                int bb = tid * CH + j;
                unsigned c = hc[bb];
                if (cum + (long long)c >= k) { bin = bb; break; }
                cum += c;
                if (WS) ab += hs[bb];
            }
            *o_bin = bin; *o_cum = cum; *o_sum = ab;
        }
    }
    __syncthreads();
}

// -------------------------------------------------------------- k0: zero
__global__ void kZero() {
    size_t n = sizeof(State) / 4;
    size_t i = (size_t)blockIdx.x * blockDim.x + threadIdx.x;
    if (i < n) ((unsigned int*)&g)[i] = 0u;
}

// --------------- k1: IoU, argmaxes, counts + fused sampled histogram
__global__ void kIoUSamp(const float* __restrict__ anchors, const float* __restrict__ tb,
                         const float* __restrict__ conf) {
    int b = blockIdx.y;
    int tid = threadIdx.x;
    int a = blockIdx.x * THR + tid;
    __shared__ float stb[TT * 4];
    __shared__ float sarea[TT];
    __shared__ unsigned long long smax[TT];
    __shared__ int snp, snn;
    __shared__ unsigned int sh[NB1];
    for (int i = tid; i < NB1; i += THR) sh[i] = 0;
    if (tid < TT * 4) stb[tid] = tb[b * TT * 4 + tid];
    if (tid < TT) smax[tid] = 0ull;
    if (tid == 0) { snp = 0; snn = 0; }
    __syncthreads();
    if (tid < TT) sarea[tid] = (stb[4 * tid + 2] - stb[4 * tid]) * (stb[4 * tid + 3] - stb[4 * tid + 1]);
    __syncthreads();

    float4 av = ((const float4*)anchors)[a];
    float aarea = (av.z - av.x) * (av.w - av.y);
    float best = -1.f;
    int bt = 0;
    unsigned long long low = (unsigned long long)(0xFFFFFFFFu - (unsigned)a);
#pragma unroll 8
    for (int t = 0; t < TT; t++) {
        float bx1 = stb[4 * t], by1 = stb[4 * t + 1];
        float bx2 = stb[4 * t + 2], by2 = stb[4 * t + 3];
        float x1 = fmaxf(av.x, bx1), y1 = fmaxf(av.y, by1);
        float x2 = fminf(av.z, bx2), y2 = fminf(av.w, by2);
        float inter = fmaxf(x2 - x1, 0.f) * fmaxf(y2 - y1, 0.f);
        float iou = inter / (aarea + sarea[t] - inter + 1e-6f);
        if (iou > best) { best = iou; bt = t; }   // strict >: first-index argmax
        unsigned long long cand = ((unsigned long long)__float_as_uint(iou) << 32) | low;
        if (cand > smax[t]) atomicMax(&smax[t], cand);
    }
    g_maxiou[b * AA + a] = best;
    g_bestt[b * AA + a] = (unsigned char)bt;

    unsigned pb = __ballot_sync(0xFFFFFFFFu, best >= 0.5f);
    unsigned nb = __ballot_sync(0xFFFFFFFFu, best < 0.4f);
    if ((tid & 31) == 0) { atomicAdd(&snp, __popc(pb)); atomicAdd(&snn, __popc(nb)); }

    // fused 1/32-sampled focal histogram (all anchors; contamination absorbed by slack)
    if (tid < THR / 32) {
        int sa = blockIdx.x * THR + tid * 32;
        const float* cp = conf + ((size_t)b * AA + sa) * CC;
        float p[CC];
#pragma unroll
        for (int c = 0; c < CC; c++) p[c] = cp[c];
        softmax21(p);
#pragma unroll
        for (int c = 0; c < CC; c++) {
            float f = focal_fn(p[c], false);
            atomicAdd(&sh[focal_bin(f)], 1u);
        }
    }
    __syncthreads();
    if (tid < TT) { unsigned long long v = smax[tid]; if (v) atomicMax(&g.packed[b][tid], v); }
    if (tid == 0) { atomicAdd(&g.numpos[b], snp); atomicAdd(&g.nneg[b], snn); }
    for (int i = tid; i < NB1; i += THR)
        if (sh[i]) atomicAdd(&g.h0[b][i], sh[i]);
}

// ------ k2: force-match, counts, blo/k, and probability threshold p_lo
__global__ void kPrep() {
    int b = blockIdx.x, tid = threadIdx.x;
    __shared__ unsigned int hc[NB1];
    __shared__ unsigned int scnt[256];
    __shared__ int s_found, s_bin;
    __shared__ long long s_cum;
    __shared__ float s_sum;
    if (tid < TT) {
        unsigned a = 0xFFFFFFFFu - (unsigned)(g.packed[b][tid] & 0xFFFFFFFFull);
        if (a < AA) {
            unsigned bit = 1u << (a & 31);
            unsigned old = atomicOr(&g.forced[b][a >> 5], bit);
            if (!(old & bit)) {
                float mi = g_maxiou[b * AA + a];
                if (mi < 0.5f) atomicAdd(&g.numpos[b], 1);
                if (mi < 0.4f) atomicAdd(&g.nneg[b], -1);
            }
        }
    }
    for (int i = tid; i < NB1; i += THR) hc[i] = g.h0[b][i];
    __syncthreads();
    long long np = g.numpos[b], nn = g.nneg[b];
    long long k = 3 * np; if (nn < k) k = nn;
    if (tid == 0) g.kval[b] = (int)k;
    if (k <= 0) { if (tid == 0) { g.blo[b] = NB1; g.plo[b] = 2.0f; } return; }
    long long target = k / 16 + 128;       // expected survivors ~ 2k + 4096
    suffix_select<NB1, false>(hc, nullptr, target, scnt, nullptr,
                              &s_found, &s_bin, &s_cum, &s_sum);
    if (tid == 0) {
        int blo = s_found ? s_bin : 0;
        g.blo[b] = blo;
        // invert focal at bin lower edge: f(p) = -0.75 p^2 log(max(1-p,1e-6))
        // monotone increasing in p -> bisection in double
        double flo = (double)__uint_as_float(((unsigned)blo) << 20);
        float plo = 0.f;
        if (flo > 0.0) {
            double lo = 0.0, hi = 1.0;
            for (int it = 0; it < 60; it++) {
                double p = 0.5 * (lo + hi);
                double pt = 1.0 - p; if (pt < 1e-6) pt = 1e-6;
                double f = -0.75 * p * p * log(pt);
                if (f < flo) lo = p; else hi = p;
            }
            plo = (float)(lo * (1.0 - 1e-4));   // conservative: over-include
        }
        g.plo[b] = plo;
    }
}

// ------------------- k3: main pass: focal, pos_sum, bbox loss, compaction
__global__ void __launch_bounds__(THR, 6)
kMain(const float* __restrict__ conf, const float* __restrict__ bbox,
      const float* __restrict__ tb, const int* __restrict__ tl) {
    int b = blockIdx.y;
    int tid = threadIdx.x;
    int lane = tid & 31;
    int a0 = blockIdx.x * THR, a = a0 + tid;
    __shared__ float sc[THR * CC];
    __shared__ float stb[TT * 4];
    __shared__ int stl[TT];
    if (tid < TT * 4) stb[tid] = tb[b * TT * 4 + tid];
    if (tid < TT) stl[tid] = tl[b * TT + tid];
    size_t cb = ((size_t)b * AA + a0) * CC;
    {   // float4 staged, coalesced (cb*4 bytes is 16B-aligned: 21*256*4 % 16 == 0)
        const float4* cp4 = (const float4*)(conf + cb);
        float4* sc4 = (float4*)sc;
#pragma unroll
        for (int i = tid; i < THR * CC / 4; i += THR) sc4[i] = cp4[i];
    }
    __syncthreads();

    float mi = g_maxiou[b * AA + a];
    bool forced = (g.forced[b][a >> 5] >> (a & 31)) & 1;
    bool pos = (mi >= 0.5f) || forced;
    bool neg = (mi < 0.4f) && !forced;

    // unnormalized softmax: e[c] = exp(x_c - m), s = sum
    float e[CC];
    float m = sc[tid * CC];
#pragma unroll
    for (int c = 1; c < CC; c++) m = fmaxf(m, sc[tid * CC + c]);
    float s = 0.f;
#pragma unroll
    for (int c = 0; c < CC; c++) { e[c] = __expf(sc[tid * CC + c] - m); s += e[c]; }

    float ps = 0.f, bb = 0.f;
    if (neg) {
        // hot path: no logs, no divisions, no ballots
        float thr = g.plo[b] * s;
#pragma unroll
        for (int c = 0; c < CC; c++) {
            if (e[c] >= thr) {                      // rare survivor
                float p = e[c] / s;
                float f = focal_fn(p, false);
                int idx = atomicAdd(&g.cnt[b], 1);
                if (idx < CAP) g_buf[b][idx] = f;
            }
        }
    } else if (pos) {
        int bt = g_bestt[b * AA + a];
        int tc = stl[bt];
        float inv = 1.0f / s;
#pragma unroll
        for (int c = 0; c < CC; c++) ps += focal_fn(e[c] * inv, c == tc);

        float4 bp = ((const float4*)bbox)[(size_t)b * AA + a];
        float t0 = stb[bt * 4], t1 = stb[bt * 4 + 1];
        float t2 = stb[bt * 4 + 2], t3 = stb[bt * 4 + 3];
        float x1 = fmaxf(bp.x, t0), y1 = fmaxf(bp.y, t1);
        float x2 = fminf(bp.z, t2), y2 = fminf(bp.w, t3);
        float inter = fmaxf(x2 - x1, 0.f) * fmaxf(y2 - y1, 0.f);
        float a1 = (bp.z - bp.x) * (bp.w - bp.y);
        float a2 = (t2 - t0) * (t3 - t1);
        float uni = a1 + a2 - inter;
        float iou = inter / (uni + 1e-6f);
        float ex1 = fminf(bp.x, t0), ey1 = fminf(bp.y, t1);
        float ex2 = fmaxf(bp.z, t2), ey2 = fmaxf(bp.w, t3);
        float enc = (ex2 - ex1) * (ey2 - ey1);
        float gl = 1.f - (iou - (enc - uni) / (enc + 1e-6f));
        float l1 = 0.f, d, ad;
        d = bp.x - t0; ad = fabsf(d); l1 += (ad < 1.f) ? 0.5f * d * d : ad - 0.5f;
        d = bp.y - t1; ad = fabsf(d); l1 += (ad < 1.f) ? 0.5f * d * d : ad - 0.5f;
        d = bp.z - t2; ad = fabsf(d); l1 += (ad < 1.f) ? 0.5f * d * d : ad - 0.5f;
        d = bp.w - t3; ad = fabsf(d); l1 += (ad < 1.f) ? 0.5f * d * d : ad - 0.5f;
        l1 *= 0.25f;
        bb = gl + 0.5f * l1;
    }
    // warp-reduce pos contributions -> 1 atomic/warp
#pragma unroll
    for (int off = 16; off > 0; off >>= 1) {
        ps += __shfl_down_sync(0xFFFFFFFFu, ps, off);
        bb += __shfl_down_sync(0xFFFFFFFFu, bb, off);
    }
    if (lane == 0) {
        if (ps != 0.f) atomicAdd(&g.possum[b], ps);
        if (bb != 0.f) atomicAdd(&g.bboxsum[b], bb);
    }
}

// ----------------- k4: exact top-k on compacted values (2-level radix)
// NOTE: must be launched with exactly 256 threads (suffix_select contract)
__global__ void kSelect() {
    int b = blockIdx.x, tid = threadIdx.x;
    __shared__ unsigned int hc[NB2];
    __shared__ float hs[NB2];
    __shared__ unsigned int scnt[256];
    __shared__ float ssum[256];
    __shared__ int s_found, s_bin;
    __shared__ long long s_cum;
    __shared__ float s_sum;
    int n = g.cnt[b];
    long long k = g.kval[b];
    long long np = g.numpos[b];
    bool bad = (n > CAP);
    float topk = 0.f;
    if (k > 0 && !bad) {
        for (int i = tid; i < NB1; i += THR) { hc[i] = 0; hs[i] = 0.f; }
        __syncthreads();
        for (int i = tid; i < n; i += THR) {
            float v = g_buf[b][i];
            int bin = focal_bin(v);
            atomicAdd(&hc[bin], 1u);
            atomicAdd(&hs[bin], v);
        }
        __syncthreads();
        suffix_select<NB1, true>(hc, hs, k, scnt, ssum, &s_found, &s_bin, &s_cum, &s_sum);
        if (!s_found) {
            bad = true;                                 // under-coverage -> fallback
        } else {
            int bstar = s_bin;
            long long rem = k - s_cum;
            float above = s_sum;
            unsigned cstar = hc[bstar];
            float sstar = hs[bstar];
            __syncthreads();
            if (rem >= (long long)cstar) {
                topk = above + sstar;                   // consume whole bin exactly
            } else {
                // level-2 refinement inside bstar
                for (int i = tid; i < NB2; i += THR) { hc[i] = 0; hs[i] = 0.f; }
                __syncthreads();
                for (int i = tid; i < n; i += THR) {
                    float v = g_buf[b][i];
                    unsigned bits = __float_as_uint(v) & 0x7FFFFFFFu;
                    if ((int)(bits >> 20) == bstar) {
                        int sb = (bits >> 8) & 0xFFF;
                        atomicAdd(&hc[sb], 1u);
                        atomicAdd(&hs[sb], v);
                    }
                }
                __syncthreads();
                suffix_select<NB2, true>(hc, hs, rem, scnt, ssum, &s_found, &s_bin, &s_cum, &s_sum);
                long long rem2 = rem - s_cum;
                float part = 0.f;
                unsigned c2 = hc[s_bin];
                if (rem2 >= (long long)c2) part = hs[s_bin];
                else if (rem2 > 0 && c2 > 0) part = (float)rem2 * (hs[s_bin] / (float)c2);
                topk = above + s_sum + part;
            }
        }
    }
    if (tid == 0) {
        if (bad && k > 0) {
            g.redo[b] = 1;
        } else {
            long long dn = np + k; if (dn < 1) dn = 1;
            g.confl[b] = (g.possum[b] + topk) / (float)dn;
        }
        g.bboxl[b] = (np > 0) ? g.bboxsum[b] / (float)np : 0.f;
    }
}

// --------- k5/k6: fallback (full histogram) — uniform early-out when idle
__global__ void kFbHist(const float* __restrict__ conf) {
    int b = blockIdx.y;
    if (g.redo[b] == 0) return;
    int tid = threadIdx.x;
    int a0 = blockIdx.x * THR, a = a0 + tid;
    __shared__ float sc[THR * CC];
    __shared__ unsigned int hc[NB1];
    __shared__ float hs[NB1];
    for (int i = tid; i < NB1; i += THR) { hc[i] = 0; hs[i] = 0.f; }
    size_t cb = ((size_t)b * AA + a0) * CC;
    for (int i = tid; i < THR * CC; i += THR) sc[i] = conf[cb + i];
    __syncthreads();
    float mi = g_maxiou[b * AA + a];
    bool forced = (g.forced[b][a >> 5] >> (a & 31)) & 1;
    if (mi < 0.4f && !forced) {
        float p[CC];
#pragma unroll
        for (int c = 0; c < CC; c++) p[c] = sc[tid * CC + c];
        softmax21(p);
#pragma unroll
        for (int c = 0; c < CC; c++) {
            float f = focal_fn(p[c], false);
            int bin = focal_bin(f);
            atomicAdd(&hc[bin], 1u);
            atomicAdd(&hs[bin], f);
        }
    }
    __syncthreads();
    for (int i = tid; i < NB1; i += THR)
        if (hc[i]) { atomicAdd(&g.fcnt[b][i], hc[i]); atomicAdd(&g.fsum[b][i], hs[i]); }
}

__global__ void kFbSel() {
    int b = blockIdx.x;
    if (g.redo[b] == 0) return;
    int tid = threadIdx.x;
    __shared__ unsigned int hc[NB1];
    __shared__ float hs[NB1];
    __shared__ unsigned int scnt[256];
    __shared__ float ssum[256];
    __shared__ int s_found, s_bin;
    __shared__ long long s_cum;
    __shared__ float s_sum;
    for (int i = tid; i < NB1; i += THR) { hc[i] = g.fcnt[b][i]; hs[i] = g.fsum[b][i]; }
    __syncthreads();
    long long k = g.kval[b], np = g.numpos[b];
    suffix_select<NB1, true>(hc, hs, k, scnt, ssum, &s_found, &s_bin, &s_cum, &s_sum);
    if (tid) return;
    float ab = s_sum;
    long long rem = k - s_cum;
    unsigned c = hc[s_bin];
    if (rem >= (long long)c) ab += hs[s_bin];
    else if (rem > 0 && c > 0) ab += (float)rem * (hs[s_bin] / (float)c);
    long long dn = np + k; if (dn < 1) dn = 1;
    g.confl[b] = (g.possum[b] + ab) / (float)dn;
}

// --------------------------------------------------------- k7: finalize
__global__ void kFinal(float* out) {
    if (threadIdx.x == 0) {
        float cs = 0.f, bs = 0.f;
        for (int b = 0; b < BB; b++) { cs += g.confl[b]; bs += g.bboxl[b]; }
        cs *= (1.0f / BB); bs *= (1.0f / BB);
        out[0] = cs + bs;
        out[1] = cs;
        out[2] = bs;
    }
}

// ---------------------------------------------------------------- launch
extern "C" void kernel_launch(void* const* d_in, const int* in_sizes, int n_in,
                              void* d_out, int out_size) {
    const float* conf = (const float*)d_in[0];
    const float* bbox = (const float*)d_in[1];
    const float* anch = (const float*)d_in[2];
    const float* tb = (const float*)d_in[3];
    const int* tl = (const int*)d_in[4];
    float* out = (float*)d_out;

    int nz = (int)(sizeof(State) / 4);
    kZero<<<(nz + 255) / 256, 256>>>();
    kIoUSamp<<<dim3(AA / THR, BB), THR>>>(anch, tb, conf);
    kPrep<<<BB, THR>>>();
    kMain<<<dim3(AA / THR, BB), THR>>>(conf, bbox, tb, tl);
    kSelect<<<BB, THR>>>();            // 256 threads: suffix_select contract
    kFbHist<<<dim3(AA / THR, BB), THR>>>(conf);
    kFbSel<<<BB, THR>>>();
    kFinal<<<1, 32>>>(out);
}

// round 6
// speedup vs baseline: 1.0001x; 1.0001x over previous
#include <cuda_runtime.h>
#include <cstdint>
#include <cstddef>

#define BB 16
#define AA 65536
#define TT 32
#define CC 21
#define NB1 2048
#define NB2 4096
#define CAP 262144
#define THR 256

struct State {
    unsigned long long packed[BB][TT];   // force-match argmax keys
    unsigned int forced[BB][AA / 32];    // forced-positive bitmask
    int numpos[BB], nneg[BB], kval[BB], blo[BB], redo[BB], cnt[BB];
    float possum[BB], bboxsum[BB], confl[BB], bboxl[BB];
    float plo[BB];                       // probability threshold (inverse focal)
    unsigned int h0[BB][NB1];            // sampled coarse histogram
    unsigned int fcnt[BB][NB1];          // fallback histogram
    float fsum[BB][NB1];
};
__device__ State g;
__device__ float g_buf[BB][CAP];         // compacted candidate focal values
__device__ float g_maxiou[BB * AA];
__device__ unsigned char g_bestt[BB * AA];

// ---------------------------------------------------------------- helpers
__device__ __forceinline__ float focal_fn(float p, bool ispos) {
    float pt = ispos ? p : 1.0f - p;
    float af = ispos ? 0.25f : 0.75f;
    float om = 1.0f - pt;
    return -af * om * om * __logf(fmaxf(pt, 1e-6f));
}

// bin index of a focal value; sign bit masked so -0.0 -> bin 0 (never OOB)
__device__ __forceinline__ int focal_bin(float f) {
    return (int)((__float_as_uint(f) & 0x7FFFFFFFu) >> 20);
}

// Block-wide (exactly 256 threads) descending bin selection over NB bins.
template <int NB, bool WS>
__device__ __forceinline__ void suffix_select(
    const unsigned* hc, const float* hs, long long k,
    unsigned* s_scnt, float* s_ssum,
    int* o_found, int* o_bin, long long* o_cum, float* o_sum)
{
    const int tid = threadIdx.x;          // requires blockDim.x == 256
    const int CH = NB / 256;
    unsigned myc = 0; float myf = 0.f;
#pragma unroll
    for (int j = 0; j < CH; j++) {
        myc += hc[tid * CH + j];
        if (WS) myf += hs[tid * CH + j];
    }
    s_scnt[tid] = myc;
    if (WS) s_ssum[tid] = myf;
    __syncthreads();
    for (int off = 1; off < 256; off <<= 1) {   // inclusive suffix scan
        unsigned vc = (tid + off < 256) ? s_scnt[tid + off] : 0u;
        float vf = 0.f;
        if (WS) vf = (tid + off < 256) ? s_ssum[tid + off] : 0.f;
        __syncthreads();
        s_scnt[tid] += vc;
        if (WS) s_ssum[tid] += vf;
        __syncthreads();
    }
    if (tid == 0) {
        *o_found = ((long long)s_scnt[0] >= k) ? 1 : 0;
        *o_bin = 0; *o_cum = 0; *o_sum = 0.f;
    }
    __syncthreads();
    if (*o_found) {
        long long S = (long long)s_scnt[tid];
        long long A = S - (long long)myc;
        if (A < k && S >= k) {                    // unique crossing chunk
            long long cum = A;
            float ab = WS ? (s_ssum[tid] - myf) : 0.f;
            int bin = tid * CH;
            for (int j = CH - 1; j >= 0; j--) {
                int bb = tid * CH + j;
                unsigned c = hc[bb];
                if (cum + (long long)c >= k) { bin = bb; break; }
                cum += c;
                if (WS) ab += hs[bb];
            }
            *o_bin = bin; *o_cum = cum; *o_sum = ab;
        }
    }
    __syncthreads();
}

// -------------------------------------------------------------- k0: zero
__global__ void kZero() {
    size_t n = sizeof(State) / 4;
    size_t i = (size_t)blockIdx.x * blockDim.x + threadIdx.x;
    if (i < n) ((unsigned int*)&g)[i] = 0u;
}

// --------------- k1: IoU, argmaxes, counts + fused sampled histogram
__global__ void kIoUSamp(const float* __restrict__ anchors, const float* __restrict__ tb,
                         const float* __restrict__ conf) {
    int b = blockIdx.y;
    int tid = threadIdx.x;
    int a = blockIdx.x * THR + tid;
    __shared__ float stb[TT * 4];
    __shared__ float sarea[TT];
    __shared__ unsigned long long smax[TT];
    __shared__ int snp, snn;
    __shared__ unsigned int sh[NB1];
    for (int i = tid; i < NB1; i += THR) sh[i] = 0;
    if (tid < TT * 4) stb[tid] = tb[b * TT * 4 + tid];
    if (tid < TT) smax[tid] = 0ull;
    if (tid == 0) { snp = 0; snn = 0; }
    __syncthreads();
    if (tid < TT) sarea[tid] = (stb[4 * tid + 2] - stb[4 * tid]) * (stb[4 * tid + 3] - stb[4 * tid + 1]);
    __syncthreads();

    float4 av = ((const float4*)anchors)[a];
    float aarea = (av.z - av.x) * (av.w - av.y);
    float best = -1.f;
    int bt = 0;
    unsigned long long low = (unsigned long long)(0xFFFFFFFFu - (unsigned)a);
#pragma unroll 8
    for (int t = 0; t < TT; t++) {
        float bx1 = stb[4 * t], by1 = stb[4 * t + 1];
        float bx2 = stb[4 * t + 2], by2 = stb[4 * t + 3];
        float x1 = fmaxf(av.x, bx1), y1 = fmaxf(av.y, by1);
        float x2 = fminf(av.z, bx2), y2 = fminf(av.w, by2);
        float inter = fmaxf(x2 - x1, 0.f) * fmaxf(y2 - y1, 0.f);
        float iou = inter / (aarea + sarea[t] - inter + 1e-6f);
        if (iou > best) { best = iou; bt = t; }   // strict >: first-index argmax
        unsigned long long cand = ((unsigned long long)__float_as_uint(iou) << 32) | low;
        if (cand > smax[t]) atomicMax(&smax[t], cand);
    }
    g_maxiou[b * AA + a] = best;
    g_bestt[b * AA + a] = (unsigned char)bt;

    unsigned pb = __ballot_sync(0xFFFFFFFFu, best >= 0.5f);
    unsigned nb = __ballot_sync(0xFFFFFFFFu, best < 0.4f);
    if ((tid & 31) == 0) { atomicAdd(&snp, __popc(pb)); atomicAdd(&snn, __popc(nb)); }

    // fused 1/32-sampled focal histogram — array-free (no register spill):
    // pass1 max, pass2 sum of exps, pass3 focal per class (reread via L1)
    if (tid < THR / 32) {
        int sa = blockIdx.x * THR + tid * 32;
        const float* cp = conf + ((size_t)b * AA + sa) * CC;
        float m = cp[0];
#pragma unroll
        for (int c = 1; c < CC; c++) m = fmaxf(m, cp[c]);
        float s = 0.f;
#pragma unroll
        for (int c = 0; c < CC; c++) s += __expf(cp[c] - m);
        float inv = 1.0f / s;
#pragma unroll
        for (int c = 0; c < CC; c++) {
            float p = __expf(cp[c] - m) * inv;
            float f = focal_fn(p, false);
            atomicAdd(&sh[focal_bin(f)], 1u);
        }
    }
    __syncthreads();
    if (tid < TT) { unsigned long long v = smax[tid]; if (v) atomicMax(&g.packed[b][tid], v); }
    if (tid == 0) { atomicAdd(&g.numpos[b], snp); atomicAdd(&g.nneg[b], snn); }
    for (int i = tid; i < NB1; i += THR)
        if (sh[i]) atomicAdd(&g.h0[b][i], sh[i]);
}

// ------ k2: force-match, counts, blo/k, and probability threshold p_lo
__global__ void kPrep() {
    int b = blockIdx.x, tid = threadIdx.x;
    __shared__ unsigned int hc[NB1];
    __shared__ unsigned int scnt[256];
    __shared__ int s_found, s_bin;
    __shared__ long long s_cum;
    __shared__ float s_sum;
    if (tid < TT) {
        unsigned a = 0xFFFFFFFFu - (unsigned)(g.packed[b][tid] & 0xFFFFFFFFull);
        if (a < AA) {
            unsigned bit = 1u << (a & 31);
            unsigned old = atomicOr(&g.forced[b][a >> 5], bit);
            if (!(old & bit)) {
                float mi = g_maxiou[b * AA + a];
                if (mi < 0.5f) atomicAdd(&g.numpos[b], 1);
                if (mi < 0.4f) atomicAdd(&g.nneg[b], -1);
            }
        }
    }
    for (int i = tid; i < NB1; i += THR) hc[i] = g.h0[b][i];
    __syncthreads();
    long long np = g.numpos[b], nn = g.nneg[b];
    long long k = 3 * np; if (nn < k) k = nn;
    if (tid == 0) g.kval[b] = (int)k;
    if (k <= 0) { if (tid == 0) { g.blo[b] = NB1; g.plo[b] = 2.0f; } return; }
    long long target = k / 16 + 128;       // expected survivors ~ 2k + 4096
    suffix_select<NB1, false>(hc, nullptr, target, scnt, nullptr,
                              &s_found, &s_bin, &s_cum, &s_sum);
    if (tid == 0) {
        int blo = s_found ? s_bin : 0;
        g.blo[b] = blo;
        // invert focal at bin lower edge: f(p) = -0.75 p^2 log(max(1-p,1e-6))
        // monotone increasing in p -> bisection in double
        double flo = (double)__uint_as_float(((unsigned)blo) << 20);
        float plo = 0.f;
        if (flo > 0.0) {
            double lo = 0.0, hi = 1.0;
            for (int it = 0; it < 60; it++) {
                double p = 0.5 * (lo + hi);
                double pt = 1.0 - p; if (pt < 1e-6) pt = 1e-6;
                double f = -0.75 * p * p * log(pt);
                if (f < flo) lo = p; else hi = p;
            }
            plo = (float)(lo * (1.0 - 1e-4));   // conservative: over-include
        }
        g.plo[b] = plo;
    }
}

// ------------------- k3: main pass: focal, pos_sum, bbox loss, compaction
// Array-free: exp values are kept IN SHARED (in-place overwrite), so no
// indexed register array exists -> no local-memory spill on the hot path.
__global__ void kMain(const float* __restrict__ conf, const float* __restrict__ bbox,
                      const float* __restrict__ tb, const int* __restrict__ tl) {
    int b = blockIdx.y;
    int tid = threadIdx.x;
    int lane = tid & 31;
    int a0 = blockIdx.x * THR, a = a0 + tid;
    __shared__ float sc[THR * CC];
    __shared__ float stb[TT * 4];
    __shared__ int stl[TT];
    if (tid < TT * 4) stb[tid] = tb[b * TT * 4 + tid];
    if (tid < TT) stl[tid] = tl[b * TT + tid];
    size_t cb = ((size_t)b * AA + a0) * CC;
    {   // float4 staged, coalesced (cb*4 bytes is 16B-aligned: 21*256*4 % 16 == 0)
        const float4* cp4 = (const float4*)(conf + cb);
        float4* sc4 = (float4*)sc;
#pragma unroll
        for (int i = tid; i < THR * CC / 4; i += THR) sc4[i] = cp4[i];
    }
    __syncthreads();

    float mi = g_maxiou[b * AA + a];
    bool forced = (g.forced[b][a >> 5] >> (a & 31)) & 1;
    bool pos = (mi >= 0.5f) || forced;
    bool neg = (mi < 0.4f) && !forced;

    float* row = sc + tid * CC;              // stride-21 rows: conflict-free
    // pass A: max
    float m = row[0];
#pragma unroll
    for (int c = 1; c < CC; c++) m = fmaxf(m, row[c]);
    // pass B: exp in place + sum  (each thread touches only its own row)
    float s = 0.f;
#pragma unroll
    for (int c = 0; c < CC; c++) { float ex = __expf(row[c] - m); row[c] = ex; s += ex; }

    float ps = 0.f, bb = 0.f;
    if (neg) {
        float thr = g.plo[b] * s;            // hot path: 21 compares, no log/div
        float inv = 1.0f / s;
#pragma unroll
        for (int c = 0; c < CC; c++) {
            if (row[c] >= thr) {             // rare survivor
                float f = focal_fn(row[c] * inv, false);
                int idx = atomicAdd(&g.cnt[b], 1);
                if (idx < CAP) g_buf[b][idx] = f;
            }
        }
    } else if (pos) {
        int bt = g_bestt[b * AA + a];
        int tc = stl[bt];
        float inv = 1.0f / s;
#pragma unroll
        for (int c = 0; c < CC; c++) ps += focal_fn(row[c] * inv, c == tc);

        float4 bp = ((const float4*)bbox)[(size_t)b * AA + a];
        float t0 = stb[bt * 4], t1 = stb[bt * 4 + 1];
        float t2 = stb[bt * 4 + 2], t3 = stb[bt * 4 + 3];
        float x1 = fmaxf(bp.x, t0), y1 = fmaxf(bp.y, t1);
        float x2 = fminf(bp.z, t2), y2 = fminf(bp.w, t3);
        float inter = fmaxf(x2 - x1, 0.f) * fmaxf(y2 - y1, 0.f);
        float a1 = (bp.z - bp.x) * (bp.w - bp.y);
        float a2 = (t2 - t0) * (t3 - t1);
        float uni = a1 + a2 - inter;
        float iou = inter / (uni + 1e-6f);
        float ex1 = fminf(bp.x, t0), ey1 = fminf(bp.y, t1);
        float ex2 = fmaxf(bp.z, t2), ey2 = fmaxf(bp.w, t3);
        float enc = (ex2 - ex1) * (ey2 - ey1);
        float gl = 1.f - (iou - (enc - uni) / (enc + 1e-6f));
        float l1 = 0.f, d, ad;
        d = bp.x - t0; ad = fabsf(d); l1 += (ad < 1.f) ? 0.5f * d * d : ad - 0.5f;
        d = bp.y - t1; ad = fabsf(d); l1 += (ad < 1.f) ? 0.5f * d * d : ad - 0.5f;
        d = bp.z - t2; ad = fabsf(d); l1 += (ad < 1.f) ? 0.5f * d * d : ad - 0.5f;
        d = bp.w - t3; ad = fabsf(d); l1 += (ad < 1.f) ? 0.5f * d * d : ad - 0.5f;
        l1 *= 0.25f;
        bb = gl + 0.5f * l1;
    }
    // warp-reduce pos contributions -> 1 atomic/warp
#pragma unroll
    for (int off = 16; off > 0; off >>= 1) {
        ps += __shfl_down_sync(0xFFFFFFFFu, ps, off);
        bb += __shfl_down_sync(0xFFFFFFFFu, bb, off);
    }
    if (lane == 0) {
        if (ps != 0.f) atomicAdd(&g.possum[b], ps);
        if (bb != 0.f) atomicAdd(&g.bboxsum[b], bb);
    }
}

// ----------------- k4: exact top-k on compacted values (2-level radix)
// NOTE: must be launched with exactly 256 threads (suffix_select contract)
__global__ void kSelect() {
    int b = blockIdx.x, tid = threadIdx.x;
    __shared__ unsigned int hc[NB2];
    __shared__ float hs[NB2];
    __shared__ unsigned int scnt[256];
    __shared__ float ssum[256];
    __shared__ int s_found, s_bin;
    __shared__ long long s_cum;
    __shared__ float s_sum;
    int n = g.cnt[b];
    long long k = g.kval[b];
    long long np = g.numpos[b];
    bool bad = (n > CAP);
    float topk = 0.f;
    if (k > 0 && !bad) {
        for (int i = tid; i < NB1; i += THR) { hc[i] = 0; hs[i] = 0.f; }
        __syncthreads();
        for (int i = tid; i < n; i += THR) {
            float v = g_buf[b][i];
            int bin = focal_bin(v);
            atomicAdd(&hc[bin], 1u);
            atomicAdd(&hs[bin], v);
        }
        __syncthreads();
        suffix_select<NB1, true>(hc, hs, k, scnt, ssum, &s_found, &s_bin, &s_cum, &s_sum);
        if (!s_found) {
            bad = true;                                 // under-coverage -> fallback
        } else {
            int bstar = s_bin;
            long long rem = k - s_cum;
            float above = s_sum;
            unsigned cstar = hc[bstar];
            float sstar = hs[bstar];
            __syncthreads();
            if (rem >= (long long)cstar) {
                topk = above + sstar;                   // consume whole bin exactly
            } else {
                // level-2 refinement inside bstar
                for (int i = tid; i < NB2; i += THR) { hc[i] = 0; hs[i] = 0.f; }
                __syncthreads();
                for (int i = tid; i < n; i += THR) {
                    float v = g_buf[b][i];
                    unsigned bits = __float_as_uint(v) & 0x7FFFFFFFu;
                    if ((int)(bits >> 20) == bstar) {
                        int sb = (bits >> 8) & 0xFFF;
                        atomicAdd(&hc[sb], 1u);
                        atomicAdd(&hs[sb], v);
                    }
                }
                __syncthreads();
                suffix_select<NB2, true>(hc, hs, rem, scnt, ssum, &s_found, &s_bin, &s_cum, &s_sum);
                long long rem2 = rem - s_cum;
                float part = 0.f;
                unsigned c2 = hc[s_bin];
                if (rem2 >= (long long)c2) part = hs[s_bin];
                else if (rem2 > 0 && c2 > 0) part = (float)rem2 * (hs[s_bin] / (float)c2);
                topk = above + s_sum + part;
            }
        }
    }
    if (tid == 0) {
        if (bad && k > 0) {
            g.redo[b] = 1;
        } else {
            long long dn = np + k; if (dn < 1) dn = 1;
            g.confl[b] = (g.possum[b] + topk) / (float)dn;
        }
        g.bboxl[b] = (np > 0) ? g.bboxsum[b] / (float)np : 0.f;
    }
}

// --------- k5/k6: fallback (full histogram) — uniform early-out when idle
__global__ void kFbHist(const float* __restrict__ conf) {
    int b = blockIdx.y;
    if (g.redo[b] == 0) return;
    int tid = threadIdx.x;
    int a0 = blockIdx.x * THR, a = a0 + tid;
    __shared__ float sc[THR * CC];
    __shared__ unsigned int hc[NB1];
    __shared__ float hs[NB1];
    for (int i = tid; i < NB1; i += THR) { hc[i] = 0; hs[i] = 0.f; }
    size_t cb = ((size_t)b * AA + a0) * CC;
    for (int i = tid; i < THR * CC; i += THR) sc[i] = conf[cb + i];
    __syncthreads();
    float mi = g_maxiou[b * AA + a];
    bool forced = (g.forced[b][a >> 5] >> (a & 31)) & 1;
    if (mi < 0.4f && !forced) {
        float* row = sc + tid * CC;
        float m = row[0];
#pragma unroll
        for (int c = 1; c < CC; c++) m = fmaxf(m, row[c]);
        float s = 0.f;
#pragma unroll
        for (int c = 0; c < CC; c++) { float ex = __expf(row[c] - m); row[c] = ex; s += ex; }
        float inv = 1.0f / s;
#pragma unroll
        for (int c = 0; c < CC; c++) {
            float f = focal_fn(row[c] * inv, false);
            int bin = focal_bin(f);
            atomicAdd(&hc[bin], 1u);
            atomicAdd(&hs[bin], f);
        }
    }
    __syncthreads();
    for (int i = tid; i < NB1; i += THR)
        if (hc[i]) { atomicAdd(&g.fcnt[b][i], hc[i]); atomicAdd(&g.fsum[b][i], hs[i]); }
}

__global__ void kFbSel() {
    int b = blockIdx.x;
    if (g.redo[b] == 0) return;
    int tid = threadIdx.x;
    __shared__ unsigned int hc[NB1];
    __shared__ float hs[NB1];
    __shared__ unsigned int scnt[256];
    __shared__ float ssum[256];
    __shared__ int s_found, s_bin;
    __shared__ long long s_cum;
    __shared__ float s_sum;
    for (int i = tid; i < NB1; i += THR) { hc[i] = g.fcnt[b][i]; hs[i] = g.fsum[b][i]; }
    __syncthreads();
    long long k = g.kval[b], np = g.numpos[b];
    suffix_select<NB1, true>(hc, hs, k, scnt, ssum, &s_found, &s_bin, &s_cum, &s_sum);
    if (tid) return;
    float ab = s_sum;
    long long rem = k - s_cum;
    unsigned c = hc[s_bin];
    if (rem >= (long long)c) ab += hs[s_bin];
    else if (rem > 0 && c > 0) ab += (float)rem * (hs[s_bin] / (float)c);
    long long dn = np + k; if (dn < 1) dn = 1;
    g.confl[b] = (g.possum[b] + ab) / (float)dn;
}

// --------------------------------------------------------- k7: finalize
__global__ void kFinal(float* out) {
    if (threadIdx.x == 0) {
        float cs = 0.f, bs = 0.f;
        for (int b = 0; b < BB; b++) { cs += g.confl[b]; bs += g.bboxl[b]; }
        cs *= (1.0f / BB); bs *= (1.0f / BB);
        out[0] = cs + bs;
        out[1] = cs;
        out[2] = bs;
    }
}

// ---------------------------------------------------------------- launch
extern "C" void kernel_launch(void* const* d_in, const int* in_sizes, int n_in,
                              void* d_out, int out_size) {
    const float* conf = (const float*)d_in[0];
    const float* bbox = (const float*)d_in[1];
    const float* anch = (const float*)d_in[2];
    const float* tb = (const float*)d_in[3];
    const int* tl = (const int*)d_in[4];
    float* out = (float*)d_out;

    int nz = (int)(sizeof(State) / 4);
    kZero<<<(nz + 255) / 256, 256>>>();
    kIoUSamp<<<dim3(AA / THR, BB), THR>>>(anch, tb, conf);
    kPrep<<<BB, THR>>>();
    kMain<<<dim3(AA / THR, BB), THR>>>(conf, bbox, tb, tl);
    kSelect<<<BB, THR>>>();            // 256 threads: suffix_select contract
    kFbHist<<<dim3(AA / THR, BB), THR>>>(conf);
    kFbSel<<<BB, THR>>>();
    kFinal<<<1, 32>>>(out);
}

// round 7
// speedup vs baseline: 1.2001x; 1.2000x over previous
#include <cuda_runtime.h>
#include <cstdint>
#include <cstddef>

#define BB 16
#define AA 65536
#define TT 32
#define CC 21
#define NB1 2048
#define NB2 4096
#define CAP 262144
#define THR 256

struct State {
    unsigned long long packed[BB][TT];   // force-match argmax keys
    unsigned int forced[BB][AA / 32];    // forced-positive bitmask
    int numpos[BB], nneg[BB], kval[BB], blo[BB], redo[BB], cnt[BB];
    float possum[BB], bboxsum[BB], confl[BB], bboxl[BB];
    float plo[BB];                       // probability threshold (inverse focal)
    unsigned int h0[BB][NB1];            // sampled coarse histogram
    unsigned int fcnt[BB][NB1];          // fallback histogram
    float fsum[BB][NB1];
};
__device__ State g;
__device__ float g_buf[BB][CAP];         // compacted candidate focal values
__device__ float g_maxiou[BB * AA];
__device__ unsigned char g_bestt[BB * AA];

// ---------------------------------------------------------------- helpers
__device__ __forceinline__ float focal_fn(float p, bool ispos) {
    float pt = ispos ? p : 1.0f - p;
    float af = ispos ? 0.25f : 0.75f;
    float om = 1.0f - pt;
    return -af * om * om * __logf(fmaxf(pt, 1e-6f));
}

// bin index of a focal value; sign bit masked so -0.0 -> bin 0 (never OOB)
__device__ __forceinline__ int focal_bin(float f) {
    return (int)((__float_as_uint(f) & 0x7FFFFFFFu) >> 20);
}

// Block-wide (exactly 256 threads) descending bin selection over NB bins.
template <int NB, bool WS>
__device__ __forceinline__ void suffix_select(
    const unsigned* hc, const float* hs, long long k,
    unsigned* s_scnt, float* s_ssum,
    int* o_found, int* o_bin, long long* o_cum, float* o_sum)
{
    const int tid = threadIdx.x;          // requires blockDim.x == 256
    const int CH = NB / 256;
    unsigned myc = 0; float myf = 0.f;
#pragma unroll
    for (int j = 0; j < CH; j++) {
        myc += hc[tid * CH + j];
        if (WS) myf += hs[tid * CH + j];
    }
    s_scnt[tid] = myc;
    if (WS) s_ssum[tid] = myf;
    __syncthreads();
    for (int off = 1; off < 256; off <<= 1) {   // inclusive suffix scan
        unsigned vc = (tid + off < 256) ? s_scnt[tid + off] : 0u;
        float vf = 0.f;
        if (WS) vf = (tid + off < 256) ? s_ssum[tid + off] : 0.f;
        __syncthreads();
        s_scnt[tid] += vc;
        if (WS) s_ssum[tid] += vf;
        __syncthreads();
    }
    if (tid == 0) {
        *o_found = ((long long)s_scnt[0] >= k) ? 1 : 0;
        *o_bin = 0; *o_cum = 0; *o_sum = 0.f;
    }
    __syncthreads();
    if (*o_found) {
        long long S = (long long)s_scnt[tid];
        long long A = S - (long long)myc;
        if (A < k && S >= k) {                    // unique crossing chunk
            long long cum = A;
            float ab = WS ? (s_ssum[tid] - myf) : 0.f;
            int bin = tid * CH;
            for (int j = CH - 1; j >= 0; j--) {
                int bb = tid * CH + j;
                unsigned c = hc[bb];
                if (cum + (long long)c >= k) { bin = bb; break; }
                cum += c;
                if (WS) ab += hs[bb];
            }
            *o_bin = bin; *o_cum = cum; *o_sum = ab;
        }
    }
    __syncthreads();
}

// -------------------------------------------------------------- k0: zero
__global__ void kZero() {
    size_t n = sizeof(State) / 4;
    size_t i = (size_t)blockIdx.x * blockDim.x + threadIdx.x;
    if (i < n) ((unsigned int*)&g)[i] = 0u;
}

// --------------- k1: IoU, argmaxes, counts + fused sampled histogram
__global__ void kIoUSamp(const float* __restrict__ anchors, const float* __restrict__ tb,
                         const float* __restrict__ conf) {
    int b = blockIdx.y;
    int tid = threadIdx.x;
    int a = blockIdx.x * THR + tid;
    __shared__ float stb[TT * 4];
    __shared__ float sarea[TT];
    __shared__ unsigned long long smax[TT];
    __shared__ int snp, snn;
    __shared__ unsigned int sh[NB1];
    for (int i = tid; i < NB1; i += THR) sh[i] = 0;
    if (tid < TT * 4) stb[tid] = tb[b * TT * 4 + tid];
    if (tid < TT) smax[tid] = 0ull;
    if (tid == 0) { snp = 0; snn = 0; }
    __syncthreads();
    if (tid < TT) sarea[tid] = (stb[4 * tid + 2] - stb[4 * tid]) * (stb[4 * tid + 3] - stb[4 * tid + 1]);
    __syncthreads();

    float4 av = ((const float4*)anchors)[a];
    float aarea = (av.z - av.x) * (av.w - av.y);
    float best = -1.f;
    int bt = 0;
    unsigned long long low = (unsigned long long)(0xFFFFFFFFu - (unsigned)a);
#pragma unroll 8
    for (int t = 0; t < TT; t++) {
        float bx1 = stb[4 * t], by1 = stb[4 * t + 1];
        float bx2 = stb[4 * t + 2], by2 = stb[4 * t + 3];
        float x1 = fmaxf(av.x, bx1), y1 = fmaxf(av.y, by1);
        float x2 = fminf(av.z, bx2), y2 = fminf(av.w, by2);
        float inter = fmaxf(x2 - x1, 0.f) * fmaxf(y2 - y1, 0.f);
        float iou = inter / (aarea + sarea[t] - inter + 1e-6f);
        if (iou > best) { best = iou; bt = t; }   // strict >: first-index argmax
        unsigned long long cand = ((unsigned long long)__float_as_uint(iou) << 32) | low;
        if (cand > smax[t]) atomicMax(&smax[t], cand);
    }
    g_maxiou[b * AA + a] = best;
    g_bestt[b * AA + a] = (unsigned char)bt;

    unsigned pb = __ballot_sync(0xFFFFFFFFu, best >= 0.5f);
    unsigned nb = __ballot_sync(0xFFFFFFFFu, best < 0.4f);
    if ((tid & 31) == 0) { atomicAdd(&snp, __popc(pb)); atomicAdd(&snn, __popc(nb)); }

    // fused 1/32-sampled focal histogram — array-free
    if (tid < THR / 32) {
        int sa = blockIdx.x * THR + tid * 32;
        const float* cp = conf + ((size_t)b * AA + sa) * CC;
        float m = cp[0];
#pragma unroll
        for (int c = 1; c < CC; c++) m = fmaxf(m, cp[c]);
        float s = 0.f;
#pragma unroll
        for (int c = 0; c < CC; c++) s += __expf(cp[c] - m);
        float inv = 1.0f / s;
#pragma unroll
        for (int c = 0; c < CC; c++) {
            float p = __expf(cp[c] - m) * inv;
            float f = focal_fn(p, false);
            atomicAdd(&sh[focal_bin(f)], 1u);
        }
    }
    __syncthreads();
    if (tid < TT) { unsigned long long v = smax[tid]; if (v) atomicMax(&g.packed[b][tid], v); }
    if (tid == 0) { atomicAdd(&g.numpos[b], snp); atomicAdd(&g.nneg[b], snn); }
    for (int i = tid; i < NB1; i += THR)
        if (sh[i]) atomicAdd(&g.h0[b][i], sh[i]);
}

// ------ k2: force-match, counts, blo/k, and probability threshold p_lo
__global__ void kPrep() {
    int b = blockIdx.x, tid = threadIdx.x;
    __shared__ unsigned int hc[NB1];
    __shared__ unsigned int scnt[256];
    __shared__ int s_found, s_bin;
    __shared__ long long s_cum;
    __shared__ float s_sum;
    if (tid < TT) {
        unsigned a = 0xFFFFFFFFu - (unsigned)(g.packed[b][tid] & 0xFFFFFFFFull);
        if (a < AA) {
            unsigned bit = 1u << (a & 31);
            unsigned old = atomicOr(&g.forced[b][a >> 5], bit);
            if (!(old & bit)) {
                float mi = g_maxiou[b * AA + a];
                if (mi < 0.5f) atomicAdd(&g.numpos[b], 1);
                if (mi < 0.4f) atomicAdd(&g.nneg[b], -1);
            }
        }
    }
    for (int i = tid; i < NB1; i += THR) hc[i] = g.h0[b][i];
    __syncthreads();
    long long np = g.numpos[b], nn = g.nneg[b];
    long long k = 3 * np; if (nn < k) k = nn;
    if (tid == 0) g.kval[b] = (int)k;
    if (k <= 0) { if (tid == 0) { g.blo[b] = NB1; g.plo[b] = 2.0f; } return; }
    long long target = k / 16 + 128;       // expected survivors ~ 2k + 4096
    suffix_select<NB1, false>(hc, nullptr, target, scnt, nullptr,
                              &s_found, &s_bin, &s_cum, &s_sum);
    if (tid == 0) {
        int blo = s_found ? s_bin : 0;
        g.blo[b] = blo;
        // invert focal at bin lower edge via FLOAT bisection (no FP64 emulation!)
        // f(p) = -0.75 p^2 log(max(1-p,1e-6)), monotone increasing in p.
        float flo = __uint_as_float(((unsigned)blo) << 20);
        float plo = 0.f;
        if (flo > 0.f) {
            float lo = 0.f, hi = 1.f;
#pragma unroll
            for (int it = 0; it < 30; it++) {
                float p = 0.5f * (lo + hi);
                float pt = fmaxf(1.f - p, 1e-6f);
                float f = -0.75f * p * p * __logf(pt);
                if (f < flo) lo = p; else hi = p;
            }
            plo = lo * (1.f - 1e-3f);   // conservative margin: over-include
        }
        g.plo[b] = plo;
    }
}

// ------------------- k3: main pass: focal, pos_sum, bbox loss, compaction
// Burst staging (6 independent LDG.128 -> 6 STS.128), metadata prefetched
// before the barrier, exp recomputed in pass C (no STS in compute phase).
__global__ void kMain(const float* __restrict__ conf, const float* __restrict__ bbox,
                      const float* __restrict__ tb, const int* __restrict__ tl) {
    int b = blockIdx.y;
    int tid = threadIdx.x;
    int lane = tid & 31;
    int a0 = blockIdx.x * THR, a = a0 + tid;
    __shared__ float sc[THR * CC];
    __shared__ float stb[TT * 4];
    __shared__ int stl[TT];

    // prefetch per-anchor metadata early (overlaps with staging LDGs)
    float mi = g_maxiou[b * AA + a];
    unsigned fword = g.forced[b][a >> 5];
    int bt = g_bestt[b * AA + a];
    float plo = g.plo[b];

    if (tid < TT * 4) stb[tid] = tb[b * TT * 4 + tid];
    if (tid < TT) stl[tid] = tl[b * TT + tid];

    // burst staging: 1344 float4 = 256*5 + 64; all 6 loads issued back-to-back
    {
        const float4* cp4 = (const float4*)(conf + ((size_t)b * AA + a0) * CC);
        float4* sc4 = (float4*)sc;
        float4 r0 = cp4[tid];
        float4 r1 = cp4[tid + 256];
        float4 r2 = cp4[tid + 512];
        float4 r3 = cp4[tid + 768];
        float4 r4 = cp4[tid + 1024];
        float4 r5;
        bool has6 = tid < (THR * CC / 4 - 1280);
        if (has6) r5 = cp4[tid + 1280];
        sc4[tid] = r0;
        sc4[tid + 256] = r1;
        sc4[tid + 512] = r2;
        sc4[tid + 768] = r3;
        sc4[tid + 1024] = r4;
        if (has6) sc4[tid + 1280] = r5;
    }
    __syncthreads();

    bool forced = (fword >> (a & 31)) & 1;
    bool pos = (mi >= 0.5f) || forced;
    bool neg = (mi < 0.4f) && !forced;

    const float* row = sc + tid * CC;        // stride-21 rows: conflict-free
    // pass A: max
    float m = row[0];
#pragma unroll
    for (int c = 1; c < CC; c++) m = fmaxf(m, row[c]);
    // pass B: sum of exps (no shared writes)
    float s = 0.f;
#pragma unroll
    for (int c = 0; c < CC; c++) s += __expf(row[c] - m);

    float ps = 0.f, bb = 0.f;
    if (neg) {
        float thr = plo * s;                 // hot path: exp + compare only
        float inv = 1.0f / s;
#pragma unroll
        for (int c = 0; c < CC; c++) {
            float ex = __expf(row[c] - m);
            if (ex >= thr) {                 // rare survivor
                float f = focal_fn(ex * inv, false);
                int idx = atomicAdd(&g.cnt[b], 1);
                if (idx < CAP) g_buf[b][idx] = f;
            }
        }
    } else if (pos) {
        int tc = stl[bt];
        float inv = 1.0f / s;
#pragma unroll
        for (int c = 0; c < CC; c++) ps += focal_fn(__expf(row[c] - m) * inv, c == tc);

        float4 bp = ((const float4*)bbox)[(size_t)b * AA + a];
        float t0 = stb[bt * 4], t1 = stb[bt * 4 + 1];
        float t2 = stb[bt * 4 + 2], t3 = stb[bt * 4 + 3];
        float x1 = fmaxf(bp.x, t0), y1 = fmaxf(bp.y, t1);
        float x2 = fminf(bp.z, t2), y2 = fminf(bp.w, t3);
        float inter = fmaxf(x2 - x1, 0.f) * fmaxf(y2 - y1, 0.f);
        float a1 = (bp.z - bp.x) * (bp.w - bp.y);
        float a2 = (t2 - t0) * (t3 - t1);
        float uni = a1 + a2 - inter;
        float iou = inter / (uni + 1e-6f);
        float ex1 = fminf(bp.x, t0), ey1 = fminf(bp.y, t1);
        float ex2 = fmaxf(bp.z, t2), ey2 = fmaxf(bp.w, t3);
        float enc = (ex2 - ex1) * (ey2 - ey1);
        float gl = 1.f - (iou - (enc - uni) / (enc + 1e-6f));
        float l1 = 0.f, d, ad;
        d = bp.x - t0; ad = fabsf(d); l1 += (ad < 1.f) ? 0.5f * d * d : ad - 0.5f;
        d = bp.y - t1; ad = fabsf(d); l1 += (ad < 1.f) ? 0.5f * d * d : ad - 0.5f;
        d = bp.z - t2; ad = fabsf(d); l1 += (ad < 1.f) ? 0.5f * d * d : ad - 0.5f;
        d = bp.w - t3; ad = fabsf(d); l1 += (ad < 1.f) ? 0.5f * d * d : ad - 0.5f;
        l1 *= 0.25f;
        bb = gl + 0.5f * l1;
    }
    // warp-reduce pos contributions -> 1 atomic/warp
#pragma unroll
    for (int off = 16; off > 0; off >>= 1) {
        ps += __shfl_down_sync(0xFFFFFFFFu, ps, off);
        bb += __shfl_down_sync(0xFFFFFFFFu, bb, off);
    }
    if (lane == 0) {
        if (ps != 0.f) atomicAdd(&g.possum[b], ps);
        if (bb != 0.f) atomicAdd(&g.bboxsum[b], bb);
    }
}

// ----------------- k4: exact top-k on compacted values (2-level radix)
// NOTE: must be launched with exactly 256 threads (suffix_select contract)
__global__ void kSelect() {
    int b = blockIdx.x, tid = threadIdx.x;
    __shared__ unsigned int hc[NB2];
    __shared__ float hs[NB2];
    __shared__ unsigned int scnt[256];
    __shared__ float ssum[256];
    __shared__ int s_found, s_bin;
    __shared__ long long s_cum;
    __shared__ float s_sum;
    int n = g.cnt[b];
    long long k = g.kval[b];
    long long np = g.numpos[b];
    bool bad = (n > CAP);
    float topk = 0.f;
    if (k > 0 && !bad) {
        for (int i = tid; i < NB1; i += THR) { hc[i] = 0; hs[i] = 0.f; }
        __syncthreads();
        for (int i = tid; i < n; i += THR) {
            float v = g_buf[b][i];
            int bin = focal_bin(v);
            atomicAdd(&hc[bin], 1u);
            atomicAdd(&hs[bin], v);
        }
        __syncthreads();
        suffix_select<NB1, true>(hc, hs, k, scnt, ssum, &s_found, &s_bin, &s_cum, &s_sum);
        if (!s_found) {
            bad = true;                                 // under-coverage -> fallback
        } else {
            int bstar = s_bin;
            long long rem = k - s_cum;
            float above = s_sum;
            unsigned cstar = hc[bstar];
            float sstar = hs[bstar];
            __syncthreads();
            if (rem >= (long long)cstar) {
                topk = above + sstar;                   // consume whole bin exactly
            } else {
                // level-2 refinement inside bstar
                for (int i = tid; i < NB2; i += THR) { hc[i] = 0; hs[i] = 0.f; }
                __syncthreads();
                for (int i = tid; i < n; i += THR) {
                    float v = g_buf[b][i];
                    unsigned bits = __float_as_uint(v) & 0x7FFFFFFFu;
                    if ((int)(bits >> 20) == bstar) {
                        int sb = (bits >> 8) & 0xFFF;
                        atomicAdd(&hc[sb], 1u);
                        atomicAdd(&hs[sb], v);
                    }
                }
                __syncthreads();
                suffix_select<NB2, true>(hc, hs, rem, scnt, ssum, &s_found, &s_bin, &s_cum, &s_sum);
                long long rem2 = rem - s_cum;
                float part = 0.f;
                unsigned c2 = hc[s_bin];
                if (rem2 >= (long long)c2) part = hs[s_bin];
                else if (rem2 > 0 && c2 > 0) part = (float)rem2 * (hs[s_bin] / (float)c2);
                topk = above + s_sum + part;
            }
        }
    }
    if (tid == 0) {
        if (bad && k > 0) {
            g.redo[b] = 1;
        } else {
            long long dn = np + k; if (dn < 1) dn = 1;
            g.confl[b] = (g.possum[b] + topk) / (float)dn;
        }
        g.bboxl[b] = (np > 0) ? g.bboxsum[b] / (float)np : 0.f;
    }
}

// --------- k5/k6: fallback (full histogram) — uniform early-out when idle
__global__ void kFbHist(const float* __restrict__ conf) {
    int b = blockIdx.y;
    if (g.redo[b] == 0) return;
    int tid = threadIdx.x;
    int a0 = blockIdx.x * THR, a = a0 + tid;
    __shared__ float sc[THR * CC];
    __shared__ unsigned int hc[NB1];
    __shared__ float hs[NB1];
    for (int i = tid; i < NB1; i += THR) { hc[i] = 0; hs[i] = 0.f; }
    size_t cb = ((size_t)b * AA + a0) * CC;
    for (int i = tid; i < THR * CC; i += THR) sc[i] = conf[cb + i];
    __syncthreads();
    float mi = g_maxiou[b * AA + a];
    bool forced = (g.forced[b][a >> 5] >> (a & 31)) & 1;
    if (mi < 0.4f && !forced) {
        float* row = sc + tid * CC;
        float m = row[0];
#pragma unroll
        for (int c = 1; c < CC; c++) m = fmaxf(m, row[c]);
        float s = 0.f;
#pragma unroll
        for (int c = 0; c < CC; c++) { float ex = __expf(row[c] - m); row[c] = ex; s += ex; }
        float inv = 1.0f / s;
#pragma unroll
        for (int c = 0; c < CC; c++) {
            float f = focal_fn(row[c] * inv, false);
            int bin = focal_bin(f);
            atomicAdd(&hc[bin], 1u);
            atomicAdd(&hs[bin], f);
        }
    }
    __syncthreads();
    for (int i = tid; i < NB1; i += THR)
        if (hc[i]) { atomicAdd(&g.fcnt[b][i], hc[i]); atomicAdd(&g.fsum[b][i], hs[i]); }
}

__global__ void kFbSel() {
    int b = blockIdx.x;
    if (g.redo[b] == 0) return;
    int tid = threadIdx.x;
    __shared__ unsigned int hc[NB1];
    __shared__ float hs[NB1];
    __shared__ unsigned int scnt[256];
    __shared__ float ssum[256];
    __shared__ int s_found, s_bin;
    __shared__ long long s_cum;
    __shared__ float s_sum;
    for (int i = tid; i < NB1; i += THR) { hc[i] = g.fcnt[b][i]; hs[i] = g.fsum[b][i]; }
    __syncthreads();
    long long k = g.kval[b], np = g.numpos[b];
    suffix_select<NB1, true>(hc, hs, k, scnt, ssum, &s_found, &s_bin, &s_cum, &s_sum);
    if (tid) return;
    float ab = s_sum;
    long long rem = k - s_cum;
    unsigned c = hc[s_bin];
    if (rem >= (long long)c) ab += hs[s_bin];
    else if (rem > 0 && c > 0) ab += (float)rem * (hs[s_bin] / (float)c);
    long long dn = np + k; if (dn < 1) dn = 1;
    g.confl[b] = (g.possum[b] + ab) / (float)dn;
}

// --------------------------------------------------------- k7: finalize
__global__ void kFinal(float* out) {
    if (threadIdx.x == 0) {
        float cs = 0.f, bs = 0.f;
        for (int b = 0; b < BB; b++) { cs += g.confl[b]; bs += g.bboxl[b]; }
        cs *= (1.0f / BB); bs *= (1.0f / BB);
        out[0] = cs + bs;
        out[1] = cs;
        out[2] = bs;
    }
}

// ---------------------------------------------------------------- launch
extern "C" void kernel_launch(void* const* d_in, const int* in_sizes, int n_in,
                              void* d_out, int out_size) {
    const float* conf = (const float*)d_in[0];
    const float* bbox = (const float*)d_in[1];
    const float* anch = (const float*)d_in[2];
    const float* tb = (const float*)d_in[3];
    const int* tl = (const int*)d_in[4];
    float* out = (float*)d_out;

    // raise shared carveout so smem-heavy kernels reach their register-limited
    // occupancy (default ~100KB carveout caps kMain at 4 blocks/SM).
    // Attribute set is idempotent + not a stream op (capture-safe, no alloc).
    cudaFuncSetAttribute((const void*)kMain,
                         cudaFuncAttributePreferredSharedMemoryCarveout, 100);
    cudaFuncSetAttribute((const void*)kIoUSamp,
                         cudaFuncAttributePreferredSharedMemoryCarveout, 100);

    int nz = (int)(sizeof(State) / 4);
    kZero<<<(nz + 255) / 256, 256>>>();
    kIoUSamp<<<dim3(AA / THR, BB), THR>>>(anch, tb, conf);
    kPrep<<<BB, THR>>>();
    kMain<<<dim3(AA / THR, BB), THR>>>(conf, bbox, tb, tl);
    kSelect<<<BB, THR>>>();            // 256 threads: suffix_select contract
    kFbHist<<<dim3(AA / THR, BB), THR>>>(conf);
    kFbSel<<<BB, THR>>>();
    kFinal<<<1, 32>>>(out);
}

// round 8
// speedup vs baseline: 1.2333x; 1.0277x over previous
#include <cuda_runtime.h>
#include <cstdint>
#include <cstddef>

#define BB 16
#define AA 65536
#define TT 32
#define CC 21
#define NB1 2048
#define NB2 4096
#define CAP 262144
#define THR 256
#define CHK 8                 // chunks per kMain block (256 anchors each)

struct State {
    unsigned long long packed[BB][TT];   // force-match argmax keys
    unsigned int forced[BB][AA / 32];    // forced-positive bitmask
    int numpos[BB], nneg[BB], kval[BB], blo[BB], redo[BB], cnt[BB];
    float possum[BB], bboxsum[BB], confl[BB], bboxl[BB];
    float plo[BB];                       // probability threshold (inverse focal)
    unsigned int h0[BB][NB1];            // sampled coarse histogram
    unsigned int fcnt[BB][NB1];          // fallback histogram
    float fsum[BB][NB1];
};
__device__ State g;
__device__ float g_buf[BB][CAP];         // compacted candidate focal values
__device__ float g_maxiou[BB * AA];
__device__ unsigned char g_bestt[BB * AA];

// ---------------------------------------------------------------- helpers
__device__ __forceinline__ float focal_fn(float p, bool ispos) {
    float pt = ispos ? p : 1.0f - p;
    float af = ispos ? 0.25f : 0.75f;
    float om = 1.0f - pt;
    return -af * om * om * __logf(fmaxf(pt, 1e-6f));
}

__device__ __forceinline__ int focal_bin(float f) {
    return (int)((__float_as_uint(f) & 0x7FFFFFFFu) >> 20);
}

// Block-wide (exactly 256 threads) descending bin selection over NB bins.
template <int NB, bool WS>
__device__ __forceinline__ void suffix_select(
    const unsigned* hc, const float* hs, long long k,
    unsigned* s_scnt, float* s_ssum,
    int* o_found, int* o_bin, long long* o_cum, float* o_sum)
{
    const int tid = threadIdx.x;          // requires blockDim.x == 256
    const int CH = NB / 256;
    unsigned myc = 0; float myf = 0.f;
#pragma unroll
    for (int j = 0; j < CH; j++) {
        myc += hc[tid * CH + j];
        if (WS) myf += hs[tid * CH + j];
    }
    s_scnt[tid] = myc;
    if (WS) s_ssum[tid] = myf;
    __syncthreads();
    for (int off = 1; off < 256; off <<= 1) {   // inclusive suffix scan
        unsigned vc = (tid + off < 256) ? s_scnt[tid + off] : 0u;
        float vf = 0.f;
        if (WS) vf = (tid + off < 256) ? s_ssum[tid + off] : 0.f;
        __syncthreads();
        s_scnt[tid] += vc;
        if (WS) s_ssum[tid] += vf;
        __syncthreads();
    }
    if (tid == 0) {
        *o_found = ((long long)s_scnt[0] >= k) ? 1 : 0;
        *o_bin = 0; *o_cum = 0; *o_sum = 0.f;
    }
    __syncthreads();
    if (*o_found) {
        long long S = (long long)s_scnt[tid];
        long long A = S - (long long)myc;
        if (A < k && S >= k) {                    // unique crossing chunk
            long long cum = A;
            float ab = WS ? (s_ssum[tid] - myf) : 0.f;
            int bin = tid * CH;
            for (int j = CH - 1; j >= 0; j--) {
                int bb = tid * CH + j;
                unsigned c = hc[bb];
                if (cum + (long long)c >= k) { bin = bb; break; }
                cum += c;
                if (WS) ab += hs[bb];
            }
            *o_bin = bin; *o_cum = cum; *o_sum = ab;
        }
    }
    __syncthreads();
}

// -------------------------------------------------------------- k0: zero
__global__ void kZero() {
    size_t n = sizeof(State) / 4;
    size_t i = (size_t)blockIdx.x * blockDim.x + threadIdx.x;
    if (i < n) ((unsigned int*)&g)[i] = 0u;
}

// --------------- k1: IoU, argmaxes, counts + fused sampled histogram
__global__ void kIoUSamp(const float* __restrict__ anchors, const float* __restrict__ tb,
                         const float* __restrict__ conf) {
    int b = blockIdx.y;
    int tid = threadIdx.x;
    int a = blockIdx.x * THR + tid;
    __shared__ float stb[TT * 4];
    __shared__ float sarea[TT];
    __shared__ unsigned long long smax[TT];
    __shared__ int snp, snn;
    __shared__ unsigned int sh[NB1];
    for (int i = tid; i < NB1; i += THR) sh[i] = 0;
    if (tid < TT * 4) stb[tid] = tb[b * TT * 4 + tid];
    if (tid < TT) smax[tid] = 0ull;
    if (tid == 0) { snp = 0; snn = 0; }
    __syncthreads();
    if (tid < TT) sarea[tid] = (stb[4 * tid + 2] - stb[4 * tid]) * (stb[4 * tid + 3] - stb[4 * tid + 1]);
    __syncthreads();

    float4 av = ((const float4*)anchors)[a];
    float aarea = (av.z - av.x) * (av.w - av.y);
    float best = -1.f;
    int bt = 0;
    unsigned long long low = (unsigned long long)(0xFFFFFFFFu - (unsigned)a);
#pragma unroll 8
    for (int t = 0; t < TT; t++) {
        float bx1 = stb[4 * t], by1 = stb[4 * t + 1];
        float bx2 = stb[4 * t + 2], by2 = stb[4 * t + 3];
        float x1 = fmaxf(av.x, bx1), y1 = fmaxf(av.y, by1);
        float x2 = fminf(av.z, bx2), y2 = fminf(av.w, by2);
        float inter = fmaxf(x2 - x1, 0.f) * fmaxf(y2 - y1, 0.f);
        float iou = inter / (aarea + sarea[t] - inter + 1e-6f);
        if (iou > best) { best = iou; bt = t; }   // strict >: first-index argmax
        unsigned long long cand = ((unsigned long long)__float_as_uint(iou) << 32) | low;
        if (cand > smax[t]) atomicMax(&smax[t], cand);
    }
    g_maxiou[b * AA + a] = best;
    g_bestt[b * AA + a] = (unsigned char)bt;

    unsigned pb = __ballot_sync(0xFFFFFFFFu, best >= 0.5f);
    unsigned nb = __ballot_sync(0xFFFFFFFFu, best < 0.4f);
    if ((tid & 31) == 0) { atomicAdd(&snp, __popc(pb)); atomicAdd(&snn, __popc(nb)); }

    // fused 1/32-sampled focal histogram — array-free
    if (tid < THR / 32) {
        int sa = blockIdx.x * THR + tid * 32;
        const float* cp = conf + ((size_t)b * AA + sa) * CC;
        float m = cp[0];
#pragma unroll
        for (int c = 1; c < CC; c++) m = fmaxf(m, cp[c]);
        float s = 0.f;
#pragma unroll
        for (int c = 0; c < CC; c++) s += __expf(cp[c] - m);
        float inv = 1.0f / s;
#pragma unroll
        for (int c = 0; c < CC; c++) {
            float p = __expf(cp[c] - m) * inv;
            float f = focal_fn(p, false);
            atomicAdd(&sh[focal_bin(f)], 1u);
        }
    }
    __syncthreads();
    if (tid < TT) { unsigned long long v = smax[tid]; if (v) atomicMax(&g.packed[b][tid], v); }
    if (tid == 0) { atomicAdd(&g.numpos[b], snp); atomicAdd(&g.nneg[b], snn); }
    for (int i = tid; i < NB1; i += THR)
        if (sh[i]) atomicAdd(&g.h0[b][i], sh[i]);
}

// ------ k2: force-match, counts, blo/k, and probability threshold p_lo
__global__ void kPrep() {
    int b = blockIdx.x, tid = threadIdx.x;
    __shared__ unsigned int hc[NB1];
    __shared__ unsigned int scnt[256];
    __shared__ int s_found, s_bin;
    __shared__ long long s_cum;
    __shared__ float s_sum;
    if (tid < TT) {
        unsigned a = 0xFFFFFFFFu - (unsigned)(g.packed[b][tid] & 0xFFFFFFFFull);
        if (a < AA) {
            unsigned bit = 1u << (a & 31);
            unsigned old = atomicOr(&g.forced[b][a >> 5], bit);
            if (!(old & bit)) {
                float mi = g_maxiou[b * AA + a];
                if (mi < 0.5f) atomicAdd(&g.numpos[b], 1);
                if (mi < 0.4f) atomicAdd(&g.nneg[b], -1);
            }
        }
    }
    for (int i = tid; i < NB1; i += THR) hc[i] = g.h0[b][i];
    __syncthreads();
    long long np = g.numpos[b], nn = g.nneg[b];
    long long k = 3 * np; if (nn < k) k = nn;
    if (tid == 0) g.kval[b] = (int)k;
    if (k <= 0) { if (tid == 0) { g.blo[b] = NB1; g.plo[b] = 2.0f; } return; }
    long long target = k / 16 + 128;       // expected survivors ~ 2k + 4096
    suffix_select<NB1, false>(hc, nullptr, target, scnt, nullptr,
                              &s_found, &s_bin, &s_cum, &s_sum);
    if (tid == 0) {
        int blo = s_found ? s_bin : 0;
        g.blo[b] = blo;
        // invert focal at bin lower edge via FLOAT bisection
        float flo = __uint_as_float(((unsigned)blo) << 20);
        float plo = 0.f;
        if (flo > 0.f) {
            float lo = 0.f, hi = 1.f;
#pragma unroll
            for (int it = 0; it < 30; it++) {
                float p = 0.5f * (lo + hi);
                float pt = fmaxf(1.f - p, 1e-6f);
                float f = -0.75f * p * p * __logf(pt);
                if (f < flo) lo = p; else hi = p;
            }
            plo = lo * (1.f - 1e-3f);   // conservative margin: over-include
        }
        g.plo[b] = plo;
    }
}

// ------------------- k3: main pass, PIPELINED multi-chunk double-buffer.
// 512 blocks; each owns 8 chunks of 256 anchors (all in one image since
// 8 | 256). Registers prefetch chunk j+1 while computing chunk j, keeping
// DRAM continuously busy instead of load->stall->compute waves.
__global__ void kMain(const float* __restrict__ conf, const float* __restrict__ bbox,
                      const float* __restrict__ tb, const int* __restrict__ tl) {
    const int NF4 = THR * CC / 4;             // 1344
    int tid = threadIdx.x;
    int lane = tid & 31;
    int g0 = blockIdx.x * CHK;                // first chunk id
    int b = g0 >> 8;                          // image (fixed for this block)
    __shared__ float sc[2][THR * CC];
    __shared__ float stb[TT * 4];
    __shared__ int stl[TT];
    if (tid < TT * 4) stb[tid] = tb[b * TT * 4 + tid];
    if (tid < TT) stl[tid] = tl[b * TT + tid];
    float plo = g.plo[b];
    bool has6 = tid < (NF4 - 1280);

    // prefetch chunk 0
    float4 r0, r1, r2, r3, r4, r5;
    {
        const float4* cp4 = (const float4*)(conf + ((size_t)b * AA + ((g0 & 255) << 8)) * CC);
        r0 = cp4[tid]; r1 = cp4[tid + 256]; r2 = cp4[tid + 512];
        r3 = cp4[tid + 768]; r4 = cp4[tid + 1024];
        if (has6) r5 = cp4[tid + 1280];
    }

    float psT = 0.f, bbT = 0.f;
#pragma unroll 1
    for (int j = 0; j < CHK; j++) {
        int gj = g0 + j;
        int a0 = (gj & 255) << 8;
        int a = a0 + tid;
        int cur = j & 1;
        __syncthreads();                       // buffer free (compute j-2 done)
        {
            float4* s4 = (float4*)sc[cur];
            s4[tid] = r0; s4[tid + 256] = r1; s4[tid + 512] = r2;
            s4[tid + 768] = r3; s4[tid + 1024] = r4;
            if (has6) s4[tid + 1280] = r5;
        }
        // per-anchor metadata (issued alongside next-chunk prefetch)
        float mi = g_maxiou[b * AA + a];
        unsigned fword = g.forced[b][a >> 5];
        int bt = g_bestt[b * AA + a];
        if (j + 1 < CHK) {                     // prefetch chunk j+1
            const float4* np4 = (const float4*)(conf + ((size_t)b * AA + (((gj + 1) & 255) << 8)) * CC);
            r0 = np4[tid]; r1 = np4[tid + 256]; r2 = np4[tid + 512];
            r3 = np4[tid + 768]; r4 = np4[tid + 1024];
            if (has6) r5 = np4[tid + 1280];
        }
        __syncthreads();                       // staged data visible

        bool forced = (fword >> (a & 31)) & 1;
        bool pos = (mi >= 0.5f) || forced;
        bool neg = (mi < 0.4f) && !forced;
        if (pos || neg) {
            float* row = sc[cur] + tid * CC;   // stride-21: conflict-free
            float m = row[0];
#pragma unroll
            for (int c = 1; c < CC; c++) m = fmaxf(m, row[c]);
            float s = 0.f;
#pragma unroll
            for (int c = 0; c < CC; c++) { float ex = __expf(row[c] - m); row[c] = ex; s += ex; }

            if (neg) {
                float thr = plo * s;
                float inv = 1.0f / s;
#pragma unroll
                for (int c = 0; c < CC; c++) {
                    float ex = row[c];
                    if (ex >= thr) {           // rare survivor
                        float f = focal_fn(ex * inv, false);
                        int idx = atomicAdd(&g.cnt[b], 1);
                        if (idx < CAP) g_buf[b][idx] = f;
                    }
                }
            } else {
                int tc = stl[bt];
                float inv = 1.0f / s;
#pragma unroll
                for (int c = 0; c < CC; c++) psT += focal_fn(row[c] * inv, c == tc);

                float4 bp = ((const float4*)bbox)[(size_t)b * AA + a];
                float t0 = stb[bt * 4], t1 = stb[bt * 4 + 1];
                float t2 = stb[bt * 4 + 2], t3 = stb[bt * 4 + 3];
                float x1 = fmaxf(bp.x, t0), y1 = fmaxf(bp.y, t1);
                float x2 = fminf(bp.z, t2), y2 = fminf(bp.w, t3);
                float inter = fmaxf(x2 - x1, 0.f) * fmaxf(y2 - y1, 0.f);
                float a1 = (bp.z - bp.x) * (bp.w - bp.y);
                float a2 = (t2 - t0) * (t3 - t1);
                float uni = a1 + a2 - inter;
                float iou = inter / (uni + 1e-6f);
                float ex1 = fminf(bp.x, t0), ey1 = fminf(bp.y, t1);
                float ex2 = fmaxf(bp.z, t2), ey2 = fmaxf(bp.w, t3);
                float enc = (ex2 - ex1) * (ey2 - ey1);
                float gl = 1.f - (iou - (enc - uni) / (enc + 1e-6f));
                float l1 = 0.f, d, ad;
                d = bp.x - t0; ad = fabsf(d); l1 += (ad < 1.f) ? 0.5f * d * d : ad - 0.5f;
                d = bp.y - t1; ad = fabsf(d); l1 += (ad < 1.f) ? 0.5f * d * d : ad - 0.5f;
                d = bp.z - t2; ad = fabsf(d); l1 += (ad < 1.f) ? 0.5f * d * d : ad - 0.5f;
                d = bp.w - t3; ad = fabsf(d); l1 += (ad < 1.f) ? 0.5f * d * d : ad - 0.5f;
                l1 *= 0.25f;
                bbT += gl + 0.5f * l1;
            }
        }
    }
    // one warp-reduce + atomic per warp for the whole block's 8 chunks
#pragma unroll
    for (int off = 16; off > 0; off >>= 1) {
        psT += __shfl_down_sync(0xFFFFFFFFu, psT, off);
        bbT += __shfl_down_sync(0xFFFFFFFFu, bbT, off);
    }
    if (lane == 0) {
        if (psT != 0.f) atomicAdd(&g.possum[b], psT);
        if (bbT != 0.f) atomicAdd(&g.bboxsum[b], bbT);
    }
}

// ----------------- k4: exact top-k on compacted values (2-level radix)
__global__ void kSelect() {
    int b = blockIdx.x, tid = threadIdx.x;
    __shared__ unsigned int hc[NB2];
    __shared__ float hs[NB2];
    __shared__ unsigned int scnt[256];
    __shared__ float ssum[256];
    __shared__ int s_found, s_bin;
    __shared__ long long s_cum;
    __shared__ float s_sum;
    int n = g.cnt[b];
    long long k = g.kval[b];
    long long np = g.numpos[b];
    bool bad = (n > CAP);
    float topk = 0.f;
    if (k > 0 && !bad) {
        for (int i = tid; i < NB1; i += THR) { hc[i] = 0; hs[i] = 0.f; }
        __syncthreads();
        for (int i = tid; i < n; i += THR) {
            float v = g_buf[b][i];
            int bin = focal_bin(v);
            atomicAdd(&hc[bin], 1u);
            atomicAdd(&hs[bin], v);
        }
        __syncthreads();
        suffix_select<NB1, true>(hc, hs, k, scnt, ssum, &s_found, &s_bin, &s_cum, &s_sum);
        if (!s_found) {
            bad = true;                                 // under-coverage -> fallback
        } else {
            int bstar = s_bin;
            long long rem = k - s_cum;
            float above = s_sum;
            unsigned cstar = hc[bstar];
            float sstar = hs[bstar];
            __syncthreads();
            if (rem >= (long long)cstar) {
                topk = above + sstar;
            } else {
                for (int i = tid; i < NB2; i += THR) { hc[i] = 0; hs[i] = 0.f; }
                __syncthreads();
                for (int i = tid; i < n; i += THR) {
                    float v = g_buf[b][i];
                    unsigned bits = __float_as_uint(v) & 0x7FFFFFFFu;
                    if ((int)(bits >> 20) == bstar) {
                        int sb = (bits >> 8) & 0xFFF;
                        atomicAdd(&hc[sb], 1u);
                        atomicAdd(&hs[sb], v);
                    }
                }
                __syncthreads();
                suffix_select<NB2, true>(hc, hs, rem, scnt, ssum, &s_found, &s_bin, &s_cum, &s_sum);
                long long rem2 = rem - s_cum;
                float part = 0.f;
                unsigned c2 = hc[s_bin];
                if (rem2 >= (long long)c2) part = hs[s_bin];
                else if (rem2 > 0 && c2 > 0) part = (float)rem2 * (hs[s_bin] / (float)c2);
                topk = above + s_sum + part;
            }
        }
    }
    if (tid == 0) {
        if (bad && k > 0) {
            g.redo[b] = 1;
        } else {
            long long dn = np + k; if (dn < 1) dn = 1;
            g.confl[b] = (g.possum[b] + topk) / (float)dn;
        }
        g.bboxl[b] = (np > 0) ? g.bboxsum[b] / (float)np : 0.f;
    }
}

// --------- k5/k6: fallback (full histogram) — uniform early-out when idle
__global__ void kFbHist(const float* __restrict__ conf) {
    int b = blockIdx.y;
    if (g.redo[b] == 0) return;
    int tid = threadIdx.x;
    int a0 = blockIdx.x * THR, a = a0 + tid;
    __shared__ float sc[THR * CC];
    __shared__ unsigned int hc[NB1];
    __shared__ float hs[NB1];
    for (int i = tid; i < NB1; i += THR) { hc[i] = 0; hs[i] = 0.f; }
    size_t cb = ((size_t)b * AA + a0) * CC;
    for (int i = tid; i < THR * CC; i += THR) sc[i] = conf[cb + i];
    __syncthreads();
    float mi = g_maxiou[b * AA + a];
    bool forced = (g.forced[b][a >> 5] >> (a & 31)) & 1;
    if (mi < 0.4f && !forced) {
        float* row = sc + tid * CC;
        float m = row[0];
#pragma unroll
        for (int c = 1; c < CC; c++) m = fmaxf(m, row[c]);
        float s = 0.f;
#pragma unroll
        for (int c = 0; c < CC; c++) { float ex = __expf(row[c] - m); row[c] = ex; s += ex; }
        float inv = 1.0f / s;
#pragma unroll
        for (int c = 0; c < CC; c++) {
            float f = focal_fn(row[c] * inv, false);
            int bin = focal_bin(f);
            atomicAdd(&hc[bin], 1u);
            atomicAdd(&hs[bin], f);
        }
    }
    __syncthreads();
    for (int i = tid; i < NB1; i += THR)
        if (hc[i]) { atomicAdd(&g.fcnt[b][i], hc[i]); atomicAdd(&g.fsum[b][i], hs[i]); }
}

__global__ void kFbSel() {
    int b = blockIdx.x;
    if (g.redo[b] == 0) return;
    int tid = threadIdx.x;
    __shared__ unsigned int hc[NB1];
    __shared__ float hs[NB1];
    __shared__ unsigned int scnt[256];
    __shared__ float ssum[256];
    __shared__ int s_found, s_bin;
    __shared__ long long s_cum;
    __shared__ float s_sum;
    for (int i = tid; i < NB1; i += THR) { hc[i] = g.fcnt[b][i]; hs[i] = g.fsum[b][i]; }
    __syncthreads();
    long long k = g.kval[b], np = g.numpos[b];
    suffix_select<NB1, true>(hc, hs, k, scnt, ssum, &s_found, &s_bin, &s_cum, &s_sum);
    if (tid) return;
    float ab = s_sum;
    long long rem = k - s_cum;
    unsigned c = hc[s_bin];
    if (rem >= (long long)c) ab += hs[s_bin];
    else if (rem > 0 && c > 0) ab += (float)rem * (hs[s_bin] / (float)c);
    long long dn = np + k; if (dn < 1) dn = 1;
    g.confl[b] = (g.possum[b] + ab) / (float)dn;
}

// --------------------------------------------------------- k7: finalize
__global__ void kFinal(float* out) {
    if (threadIdx.x == 0) {
        float cs = 0.f, bs = 0.f;
        for (int b = 0; b < BB; b++) { cs += g.confl[b]; bs += g.bboxl[b]; }
        cs *= (1.0f / BB); bs *= (1.0f / BB);
        out[0] = cs + bs;
        out[1] = cs;
        out[2] = bs;
    }
}

// ---------------------------------------------------------------- launch
extern "C" void kernel_launch(void* const* d_in, const int* in_sizes, int n_in,
                              void* d_out, int out_size) {
    const float* conf = (const float*)d_in[0];
    const float* bbox = (const float*)d_in[1];
    const float* anch = (const float*)d_in[2];
    const float* tb = (const float*)d_in[3];
    const int* tl = (const int*)d_in[4];
    float* out = (float*)d_out;

    cudaFuncSetAttribute((const void*)kMain,
                         cudaFuncAttributePreferredSharedMemoryCarveout, 100);
    cudaFuncSetAttribute((const void*)kIoUSamp,
                         cudaFuncAttributePreferredSharedMemoryCarveout, 100);

    int nz = (int)(sizeof(State) / 4);
    kZero<<<(nz + 255) / 256, 256>>>();
    kIoUSamp<<<dim3(AA / THR, BB), THR>>>(anch, tb, conf);
    kPrep<<<BB, THR>>>();
    kMain<<<(BB * AA / THR) / CHK, THR>>>(conf, bbox, tb, tl);   // 512 blocks
    kSelect<<<BB, THR>>>();            // 256 threads: suffix_select contract
    kFbHist<<<dim3(AA / THR, BB), THR>>>(conf);
    kFbSel<<<BB, THR>>>();
    kFinal<<<1, 32>>>(out);
}

// round 9
// speedup vs baseline: 2.0622x; 1.6721x over previous
#include <cuda_runtime.h>
#include <cstdint>
#include <cstddef>

#define BB 16
#define AA 65536
#define TT 32
#define CC 21
#define NB1 2048
#define NB2 4096
#define CAP 262144
#define THR 256
#define CHK 8                 // chunks per kMain block (256 anchors each)
#define SBC 1024              // shared survivor staging capacity

struct State {
    unsigned long long packed[BB][TT];   // force-match argmax keys
    unsigned int forced[BB][AA / 32];    // forced-positive bitmask
    int numpos[BB], nneg[BB], kval[BB], blo[BB], redo[BB], cnt[BB];
    float possum[BB], bboxsum[BB], confl[BB], bboxl[BB];
    float plo[BB];                       // probability threshold (inverse focal)
    unsigned int h0[BB][NB1];            // sampled coarse histogram
    unsigned int fcnt[BB][NB1];          // fallback histogram
    float fsum[BB][NB1];
};
__device__ State g;
__device__ float g_buf[BB][CAP];         // compacted candidate focal values
__device__ float g_maxiou[BB * AA];
__device__ unsigned char g_bestt[BB * AA];

// ---------------------------------------------------------------- helpers
__device__ __forceinline__ float focal_fn(float p, bool ispos) {
    float pt = ispos ? p : 1.0f - p;
    float af = ispos ? 0.25f : 0.75f;
    float om = 1.0f - pt;
    return -af * om * om * __logf(fmaxf(pt, 1e-6f));
}

__device__ __forceinline__ int focal_bin(float f) {
    return (int)((__float_as_uint(f) & 0x7FFFFFFFu) >> 20);
}

// Block-wide (exactly 256 threads) descending bin selection over NB bins.
template <int NB, bool WS>
__device__ __forceinline__ void suffix_select(
    const unsigned* hc, const float* hs, long long k,
    unsigned* s_scnt, float* s_ssum,
    int* o_found, int* o_bin, long long* o_cum, float* o_sum)
{
    const int tid = threadIdx.x;          // requires blockDim.x == 256
    const int CH = NB / 256;
    unsigned myc = 0; float myf = 0.f;
#pragma unroll
    for (int j = 0; j < CH; j++) {
        myc += hc[tid * CH + j];
        if (WS) myf += hs[tid * CH + j];
    }
    s_scnt[tid] = myc;
    if (WS) s_ssum[tid] = myf;
    __syncthreads();
    for (int off = 1; off < 256; off <<= 1) {   // inclusive suffix scan
        unsigned vc = (tid + off < 256) ? s_scnt[tid + off] : 0u;
        float vf = 0.f;
        if (WS) vf = (tid + off < 256) ? s_ssum[tid + off] : 0.f;
        __syncthreads();
        s_scnt[tid] += vc;
        if (WS) s_ssum[tid] += vf;
        __syncthreads();
    }
    if (tid == 0) {
        *o_found = ((long long)s_scnt[0] >= k) ? 1 : 0;
        *o_bin = 0; *o_cum = 0; *o_sum = 0.f;
    }
    __syncthreads();
    if (*o_found) {
        long long S = (long long)s_scnt[tid];
        long long A = S - (long long)myc;
        if (A < k && S >= k) {                    // unique crossing chunk
            long long cum = A;
            float ab = WS ? (s_ssum[tid] - myf) : 0.f;
            int bin = tid * CH;
            for (int j = CH - 1; j >= 0; j--) {
                int bb = tid * CH + j;
                unsigned c = hc[bb];
                if (cum + (long long)c >= k) { bin = bb; break; }
                cum += c;
                if (WS) ab += hs[bb];
            }
            *o_bin = bin; *o_cum = cum; *o_sum = ab;
        }
    }
    __syncthreads();
}

// -------------------------------------------------------------- k0: zero
__global__ void kZero() {
    size_t n = sizeof(State) / 4;
    size_t i = (size_t)blockIdx.x * blockDim.x + threadIdx.x;
    if (i < n) ((unsigned int*)&g)[i] = 0u;
}

// --------------- k1: IoU, argmaxes, counts + fused sampled histogram
__global__ void kIoUSamp(const float* __restrict__ anchors, const float* __restrict__ tb,
                         const float* __restrict__ conf) {
    int b = blockIdx.y;
    int tid = threadIdx.x;
    int a = blockIdx.x * THR + tid;
    __shared__ float stb[TT * 4];
    __shared__ float sarea[TT];
    __shared__ unsigned long long smax[TT];
    __shared__ int snp, snn;
    __shared__ unsigned int sh[NB1];
    for (int i = tid; i < NB1; i += THR) sh[i] = 0;
    if (tid < TT * 4) stb[tid] = tb[b * TT * 4 + tid];
    if (tid < TT) smax[tid] = 0ull;
    if (tid == 0) { snp = 0; snn = 0; }
    __syncthreads();
    if (tid < TT) sarea[tid] = (stb[4 * tid + 2] - stb[4 * tid]) * (stb[4 * tid + 3] - stb[4 * tid + 1]);
    __syncthreads();

    float4 av = ((const float4*)anchors)[a];
    float aarea = (av.z - av.x) * (av.w - av.y);
    float best = -1.f;
    int bt = 0;
    unsigned long long low = (unsigned long long)(0xFFFFFFFFu - (unsigned)a);
#pragma unroll 8
    for (int t = 0; t < TT; t++) {
        float bx1 = stb[4 * t], by1 = stb[4 * t + 1];
        float bx2 = stb[4 * t + 2], by2 = stb[4 * t + 3];
        float x1 = fmaxf(av.x, bx1), y1 = fmaxf(av.y, by1);
        float x2 = fminf(av.z, bx2), y2 = fminf(av.w, by2);
        float inter = fmaxf(x2 - x1, 0.f) * fmaxf(y2 - y1, 0.f);
        float iou = __fdividef(inter, aarea + sarea[t] - inter + 1e-6f);
        if (iou > best) { best = iou; bt = t; }   // strict >: first-index argmax
        unsigned long long cand = ((unsigned long long)__float_as_uint(iou) << 32) | low;
        if (cand > smax[t]) atomicMax(&smax[t], cand);
    }
    g_maxiou[b * AA + a] = best;
    g_bestt[b * AA + a] = (unsigned char)bt;

    unsigned pb = __ballot_sync(0xFFFFFFFFu, best >= 0.5f);
    unsigned nb = __ballot_sync(0xFFFFFFFFu, best < 0.4f);
    if ((tid & 31) == 0) { atomicAdd(&snp, __popc(pb)); atomicAdd(&snn, __popc(nb)); }

    // fused 1/32-sampled focal histogram — array-free
    if (tid < THR / 32) {
        int sa = blockIdx.x * THR + tid * 32;
        const float* cp = conf + ((size_t)b * AA + sa) * CC;
        float m = cp[0];
#pragma unroll
        for (int c = 1; c < CC; c++) m = fmaxf(m, cp[c]);
        float s = 0.f;
#pragma unroll
        for (int c = 0; c < CC; c++) s += __expf(cp[c] - m);
        float inv = __fdividef(1.0f, s);
#pragma unroll
        for (int c = 0; c < CC; c++) {
            float p = __expf(cp[c] - m) * inv;
            float f = focal_fn(p, false);
            atomicAdd(&sh[focal_bin(f)], 1u);
        }
    }
    __syncthreads();
    if (tid < TT) { unsigned long long v = smax[tid]; if (v) atomicMax(&g.packed[b][tid], v); }
    if (tid == 0) { atomicAdd(&g.numpos[b], snp); atomicAdd(&g.nneg[b], snn); }
    for (int i = tid; i < NB1; i += THR)
        if (sh[i]) atomicAdd(&g.h0[b][i], sh[i]);
}

// ------ k2: force-match, counts, blo/k, and probability threshold p_lo
__global__ void kPrep() {
    int b = blockIdx.x, tid = threadIdx.x;
    __shared__ unsigned int hc[NB1];
    __shared__ unsigned int scnt[256];
    __shared__ int s_found, s_bin;
    __shared__ long long s_cum;
    __shared__ float s_sum;
    if (tid < TT) {
        unsigned a = 0xFFFFFFFFu - (unsigned)(g.packed[b][tid] & 0xFFFFFFFFull);
        if (a < AA) {
            unsigned bit = 1u << (a & 31);
            unsigned old = atomicOr(&g.forced[b][a >> 5], bit);
            if (!(old & bit)) {
                float mi = g_maxiou[b * AA + a];
                if (mi < 0.5f) atomicAdd(&g.numpos[b], 1);
                if (mi < 0.4f) atomicAdd(&g.nneg[b], -1);
            }
        }
    }
    for (int i = tid; i < NB1; i += THR) hc[i] = g.h0[b][i];
    __syncthreads();
    long long np = g.numpos[b], nn = g.nneg[b];
    long long k = 3 * np; if (nn < k) k = nn;
    if (tid == 0) g.kval[b] = (int)k;
    if (k <= 0) { if (tid == 0) { g.blo[b] = NB1; g.plo[b] = 2.0f; } return; }
    long long target = k / 16 + 128;       // expected survivors ~ 2k + 4096
    suffix_select<NB1, false>(hc, nullptr, target, scnt, nullptr,
                              &s_found, &s_bin, &s_cum, &s_sum);
    if (tid == 0) {
        int blo = s_found ? s_bin : 0;
        g.blo[b] = blo;
        // invert focal at bin lower edge via FLOAT bisection
        float flo = __uint_as_float(((unsigned)blo) << 20);
        float plo = 0.f;
        if (flo > 0.f) {
            float lo = 0.f, hi = 1.f;
#pragma unroll
            for (int it = 0; it < 30; it++) {
                float p = 0.5f * (lo + hi);
                float pt = fmaxf(1.f - p, 1e-6f);
                float f = -0.75f * p * p * __logf(pt);
                if (f < flo) lo = p; else hi = p;
            }
            plo = lo * (1.f - 1e-3f);   // conservative margin: over-include
        }
        g.plo[b] = plo;
    }
}

// ------------------- k3: main pass, pipelined + SHARED-BATCHED atomics.
// Survivors stage into shared sbuf; ONE global atomic per chunk per block
// (instead of one per survivor -> kills same-address LTS serialization).
__global__ void kMain(const float* __restrict__ conf, const float* __restrict__ bbox,
                      const float* __restrict__ tb, const int* __restrict__ tl) {
    const int NF4 = THR * CC / 4;             // 1344
    int tid = threadIdx.x;
    int lane = tid & 31;
    int g0 = blockIdx.x * CHK;                // first chunk id
    int b = g0 >> 8;                          // image (fixed for this block)
    __shared__ float sc[2][THR * CC];
    __shared__ float stb[TT * 4];
    __shared__ int stl[TT];
    __shared__ float sbuf[SBC];
    __shared__ int s_cnt, s_base;
    __shared__ float s_ps, s_bb;
    if (tid < TT * 4) stb[tid] = tb[b * TT * 4 + tid];
    if (tid < TT) stl[tid] = tl[b * TT + tid];
    if (tid == 0) { s_cnt = 0; s_ps = 0.f; s_bb = 0.f; }
    float plo = g.plo[b];
    bool has6 = tid < (NF4 - 1280);

    // prefetch chunk 0
    float4 r0, r1, r2, r3, r4, r5;
    {
        const float4* cp4 = (const float4*)(conf + ((size_t)b * AA + ((g0 & 255) << 8)) * CC);
        r0 = cp4[tid]; r1 = cp4[tid + 256]; r2 = cp4[tid + 512];
        r3 = cp4[tid + 768]; r4 = cp4[tid + 1024];
        if (has6) r5 = cp4[tid + 1280];
    }

    float psT = 0.f, bbT = 0.f;
#pragma unroll 1
    for (int j = 0; j < CHK; j++) {
        int gj = g0 + j;
        int a0 = (gj & 255) << 8;
        int a = a0 + tid;
        int cur = j & 1;
        __syncthreads();                       // (A) buffer free, s_cnt reset
        {
            float4* s4 = (float4*)sc[cur];
            s4[tid] = r0; s4[tid + 256] = r1; s4[tid + 512] = r2;
            s4[tid + 768] = r3; s4[tid + 1024] = r4;
            if (has6) s4[tid + 1280] = r5;
        }
        float mi = g_maxiou[b * AA + a];
        unsigned fword = g.forced[b][a >> 5];
        int bt = g_bestt[b * AA + a];
        if (j + 1 < CHK) {                     // prefetch chunk j+1
            const float4* np4 = (const float4*)(conf + ((size_t)b * AA + (((gj + 1) & 255) << 8)) * CC);
            r0 = np4[tid]; r1 = np4[tid + 256]; r2 = np4[tid + 512];
            r3 = np4[tid + 768]; r4 = np4[tid + 1024];
            if (has6) r5 = np4[tid + 1280];
        }
        __syncthreads();                       // (B) staged visible

        bool forced = (fword >> (a & 31)) & 1;
        bool pos = (mi >= 0.5f) || forced;
        bool neg = (mi < 0.4f) && !forced;
        if (pos || neg) {
            float* row = sc[cur] + tid * CC;   // stride-21: conflict-free
            float m = row[0];
#pragma unroll
            for (int c = 1; c < CC; c++) m = fmaxf(m, row[c]);
            float s = 0.f;
#pragma unroll
            for (int c = 0; c < CC; c++) { float ex = __expf(row[c] - m); row[c] = ex; s += ex; }

            if (neg) {
                float thr = plo * s;
                float inv = __fdividef(1.0f, s);
#pragma unroll
                for (int c = 0; c < CC; c++) {
                    float ex = row[c];
                    if (ex >= thr) {           // rare survivor -> shared staging
                        float f = focal_fn(ex * inv, false);
                        int idx = atomicAdd(&s_cnt, 1);
                        if (idx < SBC) sbuf[idx] = f;
                        else {                 // overflow: direct global (rare)
                            int gi = atomicAdd(&g.cnt[b], 1);
                            if (gi < CAP) g_buf[b][gi] = f;
                        }
                    }
                }
            } else {
                int tc = stl[bt];
                float inv = __fdividef(1.0f, s);
#pragma unroll
                for (int c = 0; c < CC; c++) psT += focal_fn(row[c] * inv, c == tc);

                float4 bp = ((const float4*)bbox)[(size_t)b * AA + a];
                float t0 = stb[bt * 4], t1 = stb[bt * 4 + 1];
                float t2 = stb[bt * 4 + 2], t3 = stb[bt * 4 + 3];
                float x1 = fmaxf(bp.x, t0), y1 = fmaxf(bp.y, t1);
                float x2 = fminf(bp.z, t2), y2 = fminf(bp.w, t3);
                float inter = fmaxf(x2 - x1, 0.f) * fmaxf(y2 - y1, 0.f);
                float a1 = (bp.z - bp.x) * (bp.w - bp.y);
                float a2 = (t2 - t0) * (t3 - t1);
                float uni = a1 + a2 - inter;
                float iou = inter / (uni + 1e-6f);
                float ex1 = fminf(bp.x, t0), ey1 = fminf(bp.y, t1);
                float ex2 = fmaxf(bp.z, t2), ey2 = fmaxf(bp.w, t3);
                float enc = (ex2 - ex1) * (ey2 - ey1);
                float gl = 1.f - (iou - (enc - uni) / (enc + 1e-6f));
                float l1 = 0.f, d, ad;
                d = bp.x - t0; ad = fabsf(d); l1 += (ad < 1.f) ? 0.5f * d * d : ad - 0.5f;
                d = bp.y - t1; ad = fabsf(d); l1 += (ad < 1.f) ? 0.5f * d * d : ad - 0.5f;
                d = bp.z - t2; ad = fabsf(d); l1 += (ad < 1.f) ? 0.5f * d * d : ad - 0.5f;
                d = bp.w - t3; ad = fabsf(d); l1 += (ad < 1.f) ? 0.5f * d * d : ad - 0.5f;
                l1 *= 0.25f;
                bbT += gl + 0.5f * l1;
            }
        }
        __syncthreads();                       // (C) survivors all staged
        int nf = s_cnt; if (nf > SBC) nf = SBC;
        if (tid == 0 && nf > 0) s_base = atomicAdd(&g.cnt[b], nf);
        __syncthreads();                       // (D) base visible
        if (nf > 0) {
            int base = s_base;
            for (int i = tid; i < nf; i += THR)
                if (base + i < CAP) g_buf[b][base + i] = sbuf[i];
        }
        if (tid == 0) s_cnt = 0;               // ordered by sync (A) next iter
    }
    // block-level reduction: warp-reduce -> shared -> ONE atomic pair/block
#pragma unroll
    for (int off = 16; off > 0; off >>= 1) {
        psT += __shfl_down_sync(0xFFFFFFFFu, psT, off);
        bbT += __shfl_down_sync(0xFFFFFFFFu, bbT, off);
    }
    if (lane == 0) {
        if (psT != 0.f) atomicAdd(&s_ps, psT);
        if (bbT != 0.f) atomicAdd(&s_bb, bbT);
    }
    __syncthreads();
    if (tid == 0) {
        if (s_ps != 0.f) atomicAdd(&g.possum[b], s_ps);
        if (s_bb != 0.f) atomicAdd(&g.bboxsum[b], s_bb);
    }
}

// ----------------- k4: exact top-k on compacted values (2-level radix)
__global__ void kSelect() {
    int b = blockIdx.x, tid = threadIdx.x;
    __shared__ unsigned int hc[NB2];
    __shared__ float hs[NB2];
    __shared__ unsigned int scnt[256];
    __shared__ float ssum[256];
    __shared__ int s_found, s_bin;
    __shared__ long long s_cum;
    __shared__ float s_sum;
    int n = g.cnt[b];
    long long k = g.kval[b];
    long long np = g.numpos[b];
    bool bad = (n > CAP);
    float topk = 0.f;
    if (k > 0 && !bad) {
        for (int i = tid; i < NB1; i += THR) { hc[i] = 0; hs[i] = 0.f; }
        __syncthreads();
        for (int i = tid; i < n; i += THR) {
            float v = g_buf[b][i];
            int bin = focal_bin(v);
            atomicAdd(&hc[bin], 1u);
            atomicAdd(&hs[bin], v);
        }
        __syncthreads();
        suffix_select<NB1, true>(hc, hs, k, scnt, ssum, &s_found, &s_bin, &s_cum, &s_sum);
        if (!s_found) {
            bad = true;                                 // under-coverage -> fallback
        } else {
            int bstar = s_bin;
            long long rem = k - s_cum;
            float above = s_sum;
            unsigned cstar = hc[bstar];
            float sstar = hs[bstar];
            __syncthreads();
            if (rem >= (long long)cstar) {
                topk = above + sstar;
            } else {
                for (int i = tid; i < NB2; i += THR) { hc[i] = 0; hs[i] = 0.f; }
                __syncthreads();
                for (int i = tid; i < n; i += THR) {
                    float v = g_buf[b][i];
                    unsigned bits = __float_as_uint(v) & 0x7FFFFFFFu;
                    if ((int)(bits >> 20) == bstar) {
                        int sb = (bits >> 8) & 0xFFF;
                        atomicAdd(&hc[sb], 1u);
                        atomicAdd(&hs[sb], v);
                    }
                }
                __syncthreads();
                suffix_select<NB2, true>(hc, hs, rem, scnt, ssum, &s_found, &s_bin, &s_cum, &s_sum);
                long long rem2 = rem - s_cum;
                float part = 0.f;
                unsigned c2 = hc[s_bin];
                if (rem2 >= (long long)c2) part = hs[s_bin];
                else if (rem2 > 0 && c2 > 0) part = (float)rem2 * (hs[s_bin] / (float)c2);
                topk = above + s_sum + part;
            }
        }
    }
    if (tid == 0) {
        if (bad && k > 0) {
            g.redo[b] = 1;
        } else {
            long long dn = np + k; if (dn < 1) dn = 1;
            g.confl[b] = (g.possum[b] + topk) / (float)dn;
        }
        g.bboxl[b] = (np > 0) ? g.bboxsum[b] / (float)np : 0.f;
    }
}

// --------- k5/k6: fallback (full histogram) — uniform early-out when idle
__global__ void kFbHist(const float* __restrict__ conf) {
    int b = blockIdx.y;
    if (g.redo[b] == 0) return;
    int tid = threadIdx.x;
    int a0 = blockIdx.x * THR, a = a0 + tid;
    __shared__ float sc[THR * CC];
    __shared__ unsigned int hc[NB1];
    __shared__ float hs[NB1];
    for (int i = tid; i < NB1; i += THR) { hc[i] = 0; hs[i] = 0.f; }
    size_t cb = ((size_t)b * AA + a0) * CC;
    for (int i = tid; i < THR * CC; i += THR) sc[i] = conf[cb + i];
    __syncthreads();
    float mi = g_maxiou[b * AA + a];
    bool forced = (g.forced[b][a >> 5] >> (a & 31)) & 1;
    if (mi < 0.4f && !forced) {
        float* row = sc + tid * CC;
        float m = row[0];
#pragma unroll
        for (int c = 1; c < CC; c++) m = fmaxf(m, row[c]);
        float s = 0.f;
#pragma unroll
        for (int c = 0; c < CC; c++) { float ex = __expf(row[c] - m); row[c] = ex; s += ex; }
        float inv = 1.0f / s;
#pragma unroll
        for (int c = 0; c < CC; c++) {
            float f = focal_fn(row[c] * inv, false);
            int bin = focal_bin(f);
            atomicAdd(&hc[bin], 1u);
            atomicAdd(&hs[bin], f);
        }
    }
    __syncthreads();
    for (int i = tid; i < NB1; i += THR)
        if (hc[i]) { atomicAdd(&g.fcnt[b][i], hc[i]); atomicAdd(&g.fsum[b][i], hs[i]); }
}

__global__ void kFbSel() {
    int b = blockIdx.x;
    if (g.redo[b] == 0) return;
    int tid = threadIdx.x;
    __shared__ unsigned int hc[NB1];
    __shared__ float hs[NB1];
    __shared__ unsigned int scnt[256];
    __shared__ float ssum[256];
    __shared__ int s_found, s_bin;
    __shared__ long long s_cum;
    __shared__ float s_sum;
    for (int i = tid; i < NB1; i += THR) { hc[i] = g.fcnt[b][i]; hs[i] = g.fsum[b][i]; }
    __syncthreads();
    long long k = g.kval[b], np = g.numpos[b];
    suffix_select<NB1, true>(hc, hs, k, scnt, ssum, &s_found, &s_bin, &s_cum, &s_sum);
    if (tid) return;
    float ab = s_sum;
    long long rem = k - s_cum;
    unsigned c = hc[s_bin];
    if (rem >= (long long)c) ab += hs[s_bin];
    else if (rem > 0 && c > 0) ab += (float)rem * (hs[s_bin] / (float)c);
    long long dn = np + k; if (dn < 1) dn = 1;
    g.confl[b] = (g.possum[b] + ab) / (float)dn;
}

// --------------------------------------------------------- k7: finalize
__global__ void kFinal(float* out) {
    if (threadIdx.x == 0) {
        float cs = 0.f, bs = 0.f;
        for (int b = 0; b < BB; b++) { cs += g.confl[b]; bs += g.bboxl[b]; }
        cs *= (1.0f / BB); bs *= (1.0f / BB);
        out[0] = cs + bs;
        out[1] = cs;
        out[2] = bs;
    }
}

// ---------------------------------------------------------------- launch
extern "C" void kernel_launch(void* const* d_in, const int* in_sizes, int n_in,
                              void* d_out, int out_size) {
    const float* conf = (const float*)d_in[0];
    const float* bbox = (const float*)d_in[1];
    const float* anch = (const float*)d_in[2];
    const float* tb = (const float*)d_in[3];
    const int* tl = (const int*)d_in[4];
    float* out = (float*)d_out;

    cudaFuncSetAttribute((const void*)kMain,
                         cudaFuncAttributePreferredSharedMemoryCarveout, 100);
    cudaFuncSetAttribute((const void*)kIoUSamp,
                         cudaFuncAttributePreferredSharedMemoryCarveout, 100);

    int nz = (int)(sizeof(State) / 4);
    kZero<<<(nz + 255) / 256, 256>>>();
    kIoUSamp<<<dim3(AA / THR, BB), THR>>>(anch, tb, conf);
    kPrep<<<BB, THR>>>();
    kMain<<<(BB * AA / THR) / CHK, THR>>>(conf, bbox, tb, tl);   // 512 blocks
    kSelect<<<BB, THR>>>();            // 256 threads: suffix_select contract
    kFbHist<<<dim3(AA / THR, BB), THR>>>(conf);
    kFbSel<<<BB, THR>>>();
    kFinal<<<1, 32>>>(out);
}

// round 10
// speedup vs baseline: 2.1618x; 1.0483x over previous
#include <cuda_runtime.h>
#include <cstdint>
#include <cstddef>

#define BB 16
#define AA 65536
#define TT 32
#define CC 21
#define NB1 2048
#define NB2 4096
#define CAP 262144
#define THR 256
#define CHK 8                 // chunks per kMain block (256 anchors each)
#define SBC 1024              // shared survivor staging capacity

struct State {
    unsigned long long packed[BB][TT];   // force-match argmax keys
    unsigned int forced[BB][AA / 32];    // forced-positive bitmask
    int numpos[BB], nneg[BB], kval[BB], blo[BB], redo[BB], cnt[BB];
    float possum[BB], bboxsum[BB], confl[BB], bboxl[BB];
    float plo[BB];                       // probability threshold (inverse focal)
    unsigned int h0[BB][NB1];            // sampled coarse histogram
    // ---- below here NOT zeroed by kZero (fully overwritten when used) ----
    unsigned int fcnt[BB][NB1];          // fallback histogram (kFbHist stores)
    float fsum[BB][NB1];
};
__device__ State g;
__device__ float g_buf[BB][CAP];         // compacted candidate focal values
__device__ float g_maxiou[BB * AA];
__device__ unsigned char g_bestt[BB * AA];

// ---------------------------------------------------------------- helpers
__device__ __forceinline__ float focal_fn(float p, bool ispos) {
    float pt = ispos ? p : 1.0f - p;
    float af = ispos ? 0.25f : 0.75f;
    float om = 1.0f - pt;
    return -af * om * om * __logf(fmaxf(pt, 1e-6f));
}

__device__ __forceinline__ int focal_bin(float f) {
    return (int)((__float_as_uint(f) & 0x7FFFFFFFu) >> 20);
}

// Block-wide (exactly 256 threads) descending bin selection over NB bins.
template <int NB, bool WS>
__device__ __forceinline__ void suffix_select(
    const unsigned* hc, const float* hs, long long k,
    unsigned* s_scnt, float* s_ssum,
    int* o_found, int* o_bin, long long* o_cum, float* o_sum)
{
    const int tid = threadIdx.x;          // requires blockDim.x == 256
    const int CH = NB / 256;
    unsigned myc = 0; float myf = 0.f;
#pragma unroll
    for (int j = 0; j < CH; j++) {
        myc += hc[tid * CH + j];
        if (WS) myf += hs[tid * CH + j];
    }
    s_scnt[tid] = myc;
    if (WS) s_ssum[tid] = myf;
    __syncthreads();
    for (int off = 1; off < 256; off <<= 1) {   // inclusive suffix scan
        unsigned vc = (tid + off < 256) ? s_scnt[tid + off] : 0u;
        float vf = 0.f;
        if (WS) vf = (tid + off < 256) ? s_ssum[tid + off] : 0.f;
        __syncthreads();
        s_scnt[tid] += vc;
        if (WS) s_ssum[tid] += vf;
        __syncthreads();
    }
    if (tid == 0) {
        *o_found = ((long long)s_scnt[0] >= k) ? 1 : 0;
        *o_bin = 0; *o_cum = 0; *o_sum = 0.f;
    }
    __syncthreads();
    if (*o_found) {
        long long S = (long long)s_scnt[tid];
        long long A = S - (long long)myc;
        if (A < k && S >= k) {                    // unique crossing chunk
            long long cum = A;
            float ab = WS ? (s_ssum[tid] - myf) : 0.f;
            int bin = tid * CH;
            for (int j = CH - 1; j >= 0; j--) {
                int bb = tid * CH + j;
                unsigned c = hc[bb];
                if (cum + (long long)c >= k) { bin = bb; break; }
                cum += c;
                if (WS) ab += hs[bb];
            }
            *o_bin = bin; *o_cum = cum; *o_sum = ab;
        }
    }
    __syncthreads();
}

// -------------------------------------------------------------- k0: zero
// zero only up to fcnt (fallback arrays are fully overwritten when used)
__global__ void kZero() {
    size_t n = offsetof(State, fcnt) / 4;
    size_t i = (size_t)blockIdx.x * blockDim.x + threadIdx.x;
    if (i < n) ((unsigned int*)&g)[i] = 0u;
}

// --------------- k1: IoU (2 anchors/thread), argmaxes, counts + sampling
__global__ void kIoUSamp(const float* __restrict__ anchors, const float* __restrict__ tb,
                         const float* __restrict__ conf) {
    int b = blockIdx.y;
    int tid = threadIdx.x;
    int a0 = blockIdx.x * (2 * THR);
    int a1 = a0 + tid, a2 = a0 + THR + tid;
    __shared__ float stb[TT * 4];
    __shared__ float sarea[TT];
    __shared__ unsigned long long smax[TT];
    __shared__ int snp, snn;
    __shared__ unsigned int sh[NB1];
    for (int i = tid; i < NB1; i += THR) sh[i] = 0;
    if (tid < TT * 4) stb[tid] = tb[b * TT * 4 + tid];
    if (tid < TT) smax[tid] = 0ull;
    if (tid == 0) { snp = 0; snn = 0; }
    __syncthreads();
    if (tid < TT) sarea[tid] = (stb[4 * tid + 2] - stb[4 * tid]) * (stb[4 * tid + 3] - stb[4 * tid + 1]);
    __syncthreads();

    float4 av1 = ((const float4*)anchors)[a1];
    float4 av2 = ((const float4*)anchors)[a2];
    float ar1 = (av1.z - av1.x) * (av1.w - av1.y);
    float ar2 = (av2.z - av2.x) * (av2.w - av2.y);
    float best1 = -1.f, best2 = -1.f;
    int bt1 = 0, bt2 = 0;
    unsigned long long lo1 = (unsigned long long)(0xFFFFFFFFu - (unsigned)a1);
    unsigned long long lo2 = (unsigned long long)(0xFFFFFFFFu - (unsigned)a2);
#pragma unroll 8
    for (int t = 0; t < TT; t++) {
        float bx1 = stb[4 * t], by1 = stb[4 * t + 1];
        float bx2 = stb[4 * t + 2], by2 = stb[4 * t + 3];
        float ta = sarea[t];
        float x1 = fmaxf(av1.x, bx1), y1 = fmaxf(av1.y, by1);
        float x2 = fminf(av1.z, bx2), y2 = fminf(av1.w, by2);
        float it1 = fmaxf(x2 - x1, 0.f) * fmaxf(y2 - y1, 0.f);
        float iou1 = __fdividef(it1, ar1 + ta - it1 + 1e-6f);
        float u1 = fmaxf(av2.x, bx1), v1 = fmaxf(av2.y, by1);
        float u2 = fminf(av2.z, bx2), v2 = fminf(av2.w, by2);
        float it2 = fmaxf(u2 - u1, 0.f) * fmaxf(v2 - v1, 0.f);
        float iou2 = __fdividef(it2, ar2 + ta - it2 + 1e-6f);
        if (iou1 > best1) { best1 = iou1; bt1 = t; }   // strict >: first-index argmax
        if (iou2 > best2) { best2 = iou2; bt2 = t; }
        unsigned long long cur = smax[t];
        unsigned long long c1 = ((unsigned long long)__float_as_uint(iou1) << 32) | lo1;
        unsigned long long c2 = ((unsigned long long)__float_as_uint(iou2) << 32) | lo2;
        if (c1 > cur) atomicMax(&smax[t], c1);
        if (c2 > cur) atomicMax(&smax[t], c2);
    }
    g_maxiou[b * AA + a1] = best1;
    g_bestt[b * AA + a1] = (unsigned char)bt1;
    g_maxiou[b * AA + a2] = best2;
    g_bestt[b * AA + a2] = (unsigned char)bt2;

    unsigned pb1 = __ballot_sync(0xFFFFFFFFu, best1 >= 0.5f);
    unsigned nb1 = __ballot_sync(0xFFFFFFFFu, best1 < 0.4f);
    unsigned pb2 = __ballot_sync(0xFFFFFFFFu, best2 >= 0.5f);
    unsigned nb2 = __ballot_sync(0xFFFFFFFFu, best2 < 0.4f);
    if ((tid & 31) == 0) {
        atomicAdd(&snp, __popc(pb1) + __popc(pb2));
        atomicAdd(&snn, __popc(nb1) + __popc(nb2));
    }

    // fused 1/32-sampled focal histogram (16 sampled anchors per 512-block)
    if (tid < 16) {
        int sa = a0 + tid * 32;
        const float* cp = conf + ((size_t)b * AA + sa) * CC;
        float m = cp[0];
#pragma unroll
        for (int c = 1; c < CC; c++) m = fmaxf(m, cp[c]);
        float s = 0.f;
#pragma unroll
        for (int c = 0; c < CC; c++) s += __expf(cp[c] - m);
        float inv = __fdividef(1.0f, s);
#pragma unroll
        for (int c = 0; c < CC; c++) {
            float p = __expf(cp[c] - m) * inv;
            float f = focal_fn(p, false);
            atomicAdd(&sh[focal_bin(f)], 1u);
        }
    }
    __syncthreads();
    if (tid < TT) { unsigned long long v = smax[tid]; if (v) atomicMax(&g.packed[b][tid], v); }
    if (tid == 0) { atomicAdd(&g.numpos[b], snp); atomicAdd(&g.nneg[b], snn); }
    for (int i = tid; i < NB1; i += THR)
        if (sh[i]) atomicAdd(&g.h0[b][i], sh[i]);
}

// ------ k2: force-match, counts, blo/k, and probability threshold p_lo
__global__ void kPrep() {
    int b = blockIdx.x, tid = threadIdx.x;
    __shared__ unsigned int hc[NB1];
    __shared__ unsigned int scnt[256];
    __shared__ int s_found, s_bin;
    __shared__ long long s_cum;
    __shared__ float s_sum;
    if (tid < TT) {
        unsigned a = 0xFFFFFFFFu - (unsigned)(g.packed[b][tid] & 0xFFFFFFFFull);
        if (a < AA) {
            unsigned bit = 1u << (a & 31);
            unsigned old = atomicOr(&g.forced[b][a >> 5], bit);
            if (!(old & bit)) {
                float mi = g_maxiou[b * AA + a];
                if (mi < 0.5f) atomicAdd(&g.numpos[b], 1);
                if (mi < 0.4f) atomicAdd(&g.nneg[b], -1);
            }
        }
    }
    for (int i = tid; i < NB1; i += THR) hc[i] = g.h0[b][i];
    __syncthreads();
    long long np = g.numpos[b], nn = g.nneg[b];
    long long k = 3 * np; if (nn < k) k = nn;
    if (tid == 0) g.kval[b] = (int)k;
    if (k <= 0) { if (tid == 0) { g.blo[b] = NB1; g.plo[b] = 2.0f; } return; }
    long long target = k / 16 + 128;       // expected survivors ~ 2k + 4096
    suffix_select<NB1, false>(hc, nullptr, target, scnt, nullptr,
                              &s_found, &s_bin, &s_cum, &s_sum);
    if (tid == 0) {
        int blo = s_found ? s_bin : 0;
        g.blo[b] = blo;
        // invert focal at bin lower edge via FLOAT bisection
        float flo = __uint_as_float(((unsigned)blo) << 20);
        float plo = 0.f;
        if (flo > 0.f) {
            float lo = 0.f, hi = 1.f;
#pragma unroll
            for (int it = 0; it < 30; it++) {
                float p = 0.5f * (lo + hi);
                float pt = fmaxf(1.f - p, 1e-6f);
                float f = -0.75f * p * p * __logf(pt);
                if (f < flo) lo = p; else hi = p;
            }
            plo = lo * (1.f - 1e-3f);   // conservative margin: over-include
        }
        g.plo[b] = plo;
    }
}

// ------------------- k3: main pass, pipelined, single smem buffer,
// shared-batched atomics, exp recomputed (no STS on hot path).
__global__ void __launch_bounds__(THR, 3)
kMain(const float* __restrict__ conf, const float* __restrict__ bbox,
      const float* __restrict__ tb, const int* __restrict__ tl) {
    const int NF4 = THR * CC / 4;             // 1344
    int tid = threadIdx.x;
    int lane = tid & 31;
    int g0 = blockIdx.x * CHK;                // first chunk id
    int b = g0 >> 8;                          // image (fixed for this block)
    __shared__ float sc[THR * CC];
    __shared__ float stb[TT * 4];
    __shared__ int stl[TT];
    __shared__ float sbuf[SBC];
    __shared__ int s_cnt, s_base;
    __shared__ float s_ps, s_bb;
    if (tid < TT * 4) stb[tid] = tb[b * TT * 4 + tid];
    if (tid < TT) stl[tid] = tl[b * TT + tid];
    if (tid == 0) { s_cnt = 0; s_ps = 0.f; s_bb = 0.f; }
    float plo = g.plo[b];
    bool has6 = tid < (NF4 - 1280);

    // prefetch chunk 0
    float4 r0, r1, r2, r3, r4, r5;
    {
        const float4* cp4 = (const float4*)(conf + ((size_t)b * AA + ((g0 & 255) << 8)) * CC);
        r0 = cp4[tid]; r1 = cp4[tid + 256]; r2 = cp4[tid + 512];
        r3 = cp4[tid + 768]; r4 = cp4[tid + 1024];
        if (has6) r5 = cp4[tid + 1280];
    }

    float psT = 0.f, bbT = 0.f;
#pragma unroll 1
    for (int j = 0; j < CHK; j++) {
        int gj = g0 + j;
        int a0 = (gj & 255) << 8;
        int a = a0 + tid;
        __syncthreads();                       // (A) compute on sc done, s_cnt reset
        {
            float4* s4 = (float4*)sc;
            s4[tid] = r0; s4[tid + 256] = r1; s4[tid + 512] = r2;
            s4[tid + 768] = r3; s4[tid + 1024] = r4;
            if (has6) s4[tid + 1280] = r5;
        }
        float mi = g_maxiou[b * AA + a];
        unsigned fword = g.forced[b][a >> 5];
        int bt = g_bestt[b * AA + a];
        if (j + 1 < CHK) {                     // prefetch chunk j+1 (regs only)
            const float4* np4 = (const float4*)(conf + ((size_t)b * AA + (((gj + 1) & 255) << 8)) * CC);
            r0 = np4[tid]; r1 = np4[tid + 256]; r2 = np4[tid + 512];
            r3 = np4[tid + 768]; r4 = np4[tid + 1024];
            if (has6) r5 = np4[tid + 1280];
        }
        __syncthreads();                       // (B) staged visible

        bool forced = (fword >> (a & 31)) & 1;
        bool pos = (mi >= 0.5f) || forced;
        bool neg = (mi < 0.4f) && !forced;
        if (pos || neg) {
            const float* row = sc + tid * CC;  // stride-21: conflict-free
            float m = row[0];
#pragma unroll
            for (int c = 1; c < CC; c++) m = fmaxf(m, row[c]);
            float s = 0.f;
#pragma unroll
            for (int c = 0; c < CC; c++) s += __expf(row[c] - m);

            if (neg) {
                float thr = plo * s;
                float inv = __fdividef(1.0f, s);
#pragma unroll
                for (int c = 0; c < CC; c++) {
                    float ex = __expf(row[c] - m);
                    if (ex >= thr) {           // rare survivor -> shared staging
                        float f = focal_fn(ex * inv, false);
                        int idx = atomicAdd(&s_cnt, 1);
                        if (idx < SBC) sbuf[idx] = f;
                        else {                 // overflow: direct global (rare)
                            int gi = atomicAdd(&g.cnt[b], 1);
                            if (gi < CAP) g_buf[b][gi] = f;
                        }
                    }
                }
            } else {
                int tc = stl[bt];
                float inv = __fdividef(1.0f, s);
#pragma unroll
                for (int c = 0; c < CC; c++)
                    psT += focal_fn(__expf(row[c] - m) * inv, c == tc);

                float4 bp = ((const float4*)bbox)[(size_t)b * AA + a];
                float t0 = stb[bt * 4], t1 = stb[bt * 4 + 1];
                float t2 = stb[bt * 4 + 2], t3 = stb[bt * 4 + 3];
                float x1 = fmaxf(bp.x, t0), y1 = fmaxf(bp.y, t1);
                float x2 = fminf(bp.z, t2), y2 = fminf(bp.w, t3);
                float inter = fmaxf(x2 - x1, 0.f) * fmaxf(y2 - y1, 0.f);
                float a1 = (bp.z - bp.x) * (bp.w - bp.y);
                float a2 = (t2 - t0) * (t3 - t1);
                float uni = a1 + a2 - inter;
                float iou = inter / (uni + 1e-6f);
                float ex1 = fminf(bp.x, t0), ey1 = fminf(bp.y, t1);
                float ex2 = fmaxf(bp.z, t2), ey2 = fmaxf(bp.w, t3);
                float enc = (ex2 - ex1) * (ey2 - ey1);
                float gl = 1.f - (iou - (enc - uni) / (enc + 1e-6f));
                float l1 = 0.f, d, ad;
                d = bp.x - t0; ad = fabsf(d); l1 += (ad < 1.f) ? 0.5f * d * d : ad - 0.5f;
                d = bp.y - t1; ad = fabsf(d); l1 += (ad < 1.f) ? 0.5f * d * d : ad - 0.5f;
                d = bp.z - t2; ad = fabsf(d); l1 += (ad < 1.f) ? 0.5f * d * d : ad - 0.5f;
                d = bp.w - t3; ad = fabsf(d); l1 += (ad < 1.f) ? 0.5f * d * d : ad - 0.5f;
                l1 *= 0.25f;
                bbT += gl + 0.5f * l1;
            }
        }
        __syncthreads();                       // (C) survivors all staged
        int nf = s_cnt; if (nf > SBC) nf = SBC;
        if (tid == 0 && nf > 0) s_base = atomicAdd(&g.cnt[b], nf);
        __syncthreads();                       // (D) base visible
        if (nf > 0) {
            int base = s_base;
            for (int i = tid; i < nf; i += THR)
                if (base + i < CAP) g_buf[b][base + i] = sbuf[i];
        }
        if (tid == 0) s_cnt = 0;               // ordered by sync (A) next iter
    }
    // block-level reduction: warp-reduce -> shared -> ONE atomic pair/block
#pragma unroll
    for (int off = 16; off > 0; off >>= 1) {
        psT += __shfl_down_sync(0xFFFFFFFFu, psT, off);
        bbT += __shfl_down_sync(0xFFFFFFFFu, bbT, off);
    }
    if (lane == 0) {
        if (psT != 0.f) atomicAdd(&s_ps, psT);
        if (bbT != 0.f) atomicAdd(&s_bb, bbT);
    }
    __syncthreads();
    if (tid == 0) {
        if (s_ps != 0.f) atomicAdd(&g.possum[b], s_ps);
        if (s_bb != 0.f) atomicAdd(&g.bboxsum[b], s_bb);
    }
}

// ----------------- k4: exact top-k on compacted values (2-level radix)
__global__ void kSelect() {
    int b = blockIdx.x, tid = threadIdx.x;
    __shared__ unsigned int hc[NB2];
    __shared__ float hs[NB2];
    __shared__ unsigned int scnt[256];
    __shared__ float ssum[256];
    __shared__ int s_found, s_bin;
    __shared__ long long s_cum;
    __shared__ float s_sum;
    int n = g.cnt[b];
    long long k = g.kval[b];
    long long np = g.numpos[b];
    bool bad = (n > CAP);
    float topk = 0.f;
    if (k > 0 && !bad) {
        for (int i = tid; i < NB1; i += THR) { hc[i] = 0; hs[i] = 0.f; }
        __syncthreads();
        for (int i = tid; i < n; i += THR) {
            float v = g_buf[b][i];
            int bin = focal_bin(v);
            atomicAdd(&hc[bin], 1u);
            atomicAdd(&hs[bin], v);
        }
        __syncthreads();
        suffix_select<NB1, true>(hc, hs, k, scnt, ssum, &s_found, &s_bin, &s_cum, &s_sum);
        if (!s_found) {
            bad = true;                                 // under-coverage -> fallback
        } else {
            int bstar = s_bin;
            long long rem = k - s_cum;
            float above = s_sum;
            unsigned cstar = hc[bstar];
            float sstar = hs[bstar];
            __syncthreads();
            if (rem >= (long long)cstar) {
                topk = above + sstar;
            } else {
                for (int i = tid; i < NB2; i += THR) { hc[i] = 0; hs[i] = 0.f; }
                __syncthreads();
                for (int i = tid; i < n; i += THR) {
                    float v = g_buf[b][i];
                    unsigned bits = __float_as_uint(v) & 0x7FFFFFFFu;
                    if ((int)(bits >> 20) == bstar) {
                        int sb = (bits >> 8) & 0xFFF;
                        atomicAdd(&hc[sb], 1u);
                        atomicAdd(&hs[sb], v);
                    }
                }
                __syncthreads();
                suffix_select<NB2, true>(hc, hs, rem, scnt, ssum, &s_found, &s_bin, &s_cum, &s_sum);
                long long rem2 = rem - s_cum;
                float part = 0.f;
                unsigned c2 = hc[s_bin];
                if (rem2 >= (long long)c2) part = hs[s_bin];
                else if (rem2 > 0 && c2 > 0) part = (float)rem2 * (hs[s_bin] / (float)c2);
                topk = above + s_sum + part;
            }
        }
    }
    if (tid == 0) {
        if (bad && k > 0) {
            g.redo[b] = 1;
        } else {
            long long dn = np + k; if (dn < 1) dn = 1;
            g.confl[b] = (g.possum[b] + topk) / (float)dn;
        }
        g.bboxl[b] = (np > 0) ? g.bboxsum[b] / (float)np : 0.f;
    }
}

// --------- k5/k6: fallback — persistent (1 block/image); never taken in
// practice. Plain stores (single writer per image).
__global__ void kFbHist(const float* __restrict__ conf) {
    int b = blockIdx.x;
    if (g.redo[b] == 0) return;
    int tid = threadIdx.x;
    __shared__ unsigned int hc[NB1];
    __shared__ float hs[NB1];
    for (int i = tid; i < NB1; i += THR) { hc[i] = 0; hs[i] = 0.f; }
    __syncthreads();
    for (int ch = 0; ch < AA / THR; ch++) {
        int a = ch * THR + tid;
        float mi = g_maxiou[b * AA + a];
        bool forced = (g.forced[b][a >> 5] >> (a & 31)) & 1;
        if (mi < 0.4f && !forced) {
            const float* row = conf + ((size_t)b * AA + a) * CC;
            float m = row[0];
#pragma unroll
            for (int c = 1; c < CC; c++) m = fmaxf(m, row[c]);
            float s = 0.f;
#pragma unroll
            for (int c = 0; c < CC; c++) s += __expf(row[c] - m);
            float inv = __fdividef(1.0f, s);
#pragma unroll
            for (int c = 0; c < CC; c++) {
                float f = focal_fn(__expf(row[c] - m) * inv, false);
                int bin = focal_bin(f);
                atomicAdd(&hc[bin], 1u);
                atomicAdd(&hs[bin], f);
            }
        }
    }
    __syncthreads();
    for (int i = tid; i < NB1; i += THR) { g.fcnt[b][i] = hc[i]; g.fsum[b][i] = hs[i]; }
}

__global__ void kFbSel() {
    int b = blockIdx.x;
    if (g.redo[b] == 0) return;
    int tid = threadIdx.x;
    __shared__ unsigned int hc[NB1];
    __shared__ float hs[NB1];
    __shared__ unsigned int scnt[256];
    __shared__ float ssum[256];
    __shared__ int s_found, s_bin;
    __shared__ long long s_cum;
    __shared__ float s_sum;
    for (int i = tid; i < NB1; i += THR) { hc[i] = g.fcnt[b][i]; hs[i] = g.fsum[b][i]; }
    __syncthreads();
    long long k = g.kval[b], np = g.numpos[b];
    suffix_select<NB1, true>(hc, hs, k, scnt, ssum, &s_found, &s_bin, &s_cum, &s_sum);
    if (tid) return;
    float ab = s_sum;
    long long rem = k - s_cum;
    unsigned c = hc[s_bin];
    if (rem >= (long long)c) ab += hs[s_bin];
    else if (rem > 0 && c > 0) ab += (float)rem * (hs[s_bin] / (float)c);
    long long dn = np + k; if (dn < 1) dn = 1;
    g.confl[b] = (g.possum[b] + ab) / (float)dn;
}

// --------------------------------------------------------- k7: finalize
__global__ void kFinal(float* out) {
    if (threadIdx.x == 0) {
        float cs = 0.f, bs = 0.f;
        for (int b = 0; b < BB; b++) { cs += g.confl[b]; bs += g.bboxl[b]; }
        cs *= (1.0f / BB); bs *= (1.0f / BB);
        out[0] = cs + bs;
        out[1] = cs;
        out[2] = bs;
    }
}

// ---------------------------------------------------------------- launch
extern "C" void kernel_launch(void* const* d_in, const int* in_sizes, int n_in,
                              void* d_out, int out_size) {
    const float* conf = (const float*)d_in[0];
    const float* bbox = (const float*)d_in[1];
    const float* anch = (const float*)d_in[2];
    const float* tb = (const float*)d_in[3];
    const int* tl = (const int*)d_in[4];
    float* out = (float*)d_out;

    cudaFuncSetAttribute((const void*)kMain,
                         cudaFuncAttributePreferredSharedMemoryCarveout, 100);
    cudaFuncSetAttribute((const void*)kIoUSamp,
                         cudaFuncAttributePreferredSharedMemoryCarveout, 100);

    int nz = (int)(offsetof(State, fcnt) / 4);
    kZero<<<(nz + 255) / 256, 256>>>();
    kIoUSamp<<<dim3(AA / (2 * THR), BB), THR>>>(anch, tb, conf);
    kPrep<<<BB, THR>>>();
    kMain<<<(BB * AA / THR) / CHK, THR>>>(conf, bbox, tb, tl);   // 512 blocks
    kSelect<<<BB, THR>>>();            // 256 threads: suffix_select contract
    kFbHist<<<BB, THR>>>(conf);
    kFbSel<<<BB, THR>>>();
    kFinal<<<1, 32>>>(out);
}